// round 4
// baseline (speedup 1.0000x reference)
#include <cuda_runtime.h>
#include <math.h>

#define BATCH 1024
#define DIMF  512
#define DMH   1024   // 2*DIM
#define DIH   2048   // 2*DM
#define DTRH  64     // DM/16
#define DSH   16

// ---------------- scratch (device globals; no allocation allowed) ----------------
__device__ float g_f0[BATCH*DIMF], g_f1[BATCH*DIMF];
__device__ float g_t0[BATCH*DIMF], g_t1[BATCH*DIMF];
__device__ float g_cat[BATCH*DMH];
__device__ float g_h1[BATCH*DIMF];
__device__ float g_h2[BATCH*256];
__device__ float g_x[BATCH*DMH];
__device__ float g_xz[BATCH*2*DIH];
__device__ float g_xc[BATCH*DIH];
__device__ float g_dbc[BATCH*96];
__device__ float g_dpre[BATCH*DIH];
__device__ float g_y[BATCH*DIH];
__device__ float g_mo[BATCH*DMH];
__device__ float g_fc[BATCH*256];
__device__ float g_gate_dummy[BATCH*2];

// ---------------- generic SGEMM: C[M,N] = epi(A[M,K] @ W[N,K]^T + bias) ----------
// A row-major with leading dim lda, W row-major [N,K] (leading dim K), C compact [M,N].
// M multiple of 64, K multiple of 16 (true for all calls). N guarded.
#define BM 64
#define BN 64
#define BK 16

__global__ __launch_bounds__(256) void gemm_nt(
    const float* __restrict__ A, int lda,
    const float* __restrict__ W,
    const float* __restrict__ bias,
    float* __restrict__ C,
    int N, int Kd, int epi)
{
    __shared__ float As[BK][BM];
    __shared__ float Ws[BK][BN];
    const int tid = threadIdx.x;
    const int m0 = blockIdx.y * BM;
    const int n0 = blockIdx.x * BN;
    const int lr = tid >> 2;        // 0..63 row within tile
    const int lk = (tid & 3) * 4;   // 0,4,8,12 k offset

    const float* Aptr = A + (size_t)(m0 + lr) * lda + lk;
    const bool wvalid = (n0 + lr) < N;
    const float* Wptr = W + (size_t)(n0 + lr) * Kd + lk;

    const int ty = tid >> 4;        // 0..15 -> m micro-tile
    const int tx = tid & 15;        // 0..15 -> n micro-tile

    float acc[4][4];
#pragma unroll
    for (int i = 0; i < 4; i++)
#pragma unroll
        for (int j = 0; j < 4; j++) acc[i][j] = 0.f;

    for (int k0 = 0; k0 < Kd; k0 += BK) {
        float4 av = *(const float4*)(Aptr + k0);
        float4 wv = wvalid ? *(const float4*)(Wptr + k0) : make_float4(0.f,0.f,0.f,0.f);
        __syncthreads();
        As[lk+0][lr] = av.x; As[lk+1][lr] = av.y; As[lk+2][lr] = av.z; As[lk+3][lr] = av.w;
        Ws[lk+0][lr] = wv.x; Ws[lk+1][lr] = wv.y; Ws[lk+2][lr] = wv.z; Ws[lk+3][lr] = wv.w;
        __syncthreads();
#pragma unroll
        for (int kk = 0; kk < BK; kk++) {
            float4 a = *(const float4*)&As[kk][ty*4];
            float4 w = *(const float4*)&Ws[kk][tx*4];
            float ar[4] = {a.x, a.y, a.z, a.w};
            float wr[4] = {w.x, w.y, w.z, w.w};
#pragma unroll
            for (int i = 0; i < 4; i++)
#pragma unroll
                for (int j = 0; j < 4; j++) acc[i][j] += ar[i] * wr[j];
        }
    }

#pragma unroll
    for (int i = 0; i < 4; i++) {
        const int m = m0 + ty*4 + i;
#pragma unroll
        for (int j = 0; j < 4; j++) {
            const int n = n0 + tx*4 + j;
            if (n < N) {
                float v = acc[i][j];
                if (bias) v += bias[n];
                if (epi == 1) v = fmaxf(v, 0.f);
                C[(size_t)m * N + n] = v;
            }
        }
    }
}

// ---------------- LayerNorm (optionally with residual add) -----------------------
__global__ __launch_bounds__(256) void ln_kernel(
    const float* __restrict__ X, const float* __restrict__ R,
    const float* __restrict__ g, const float* __restrict__ b,
    float* __restrict__ Y, int cols)
{
    const int row = blockIdx.x;
    const int tid = threadIdx.x;
    const float* x = X + (size_t)row * cols;
    const float* r = R ? R + (size_t)row * cols : nullptr;
    __shared__ float red[256];
    __shared__ float s_mean, s_rstd;

    float s = 0.f;
    for (int i = tid; i < cols; i += 256) {
        float v = x[i] + (r ? r[i] : 0.f);
        s += v;
    }
    red[tid] = s; __syncthreads();
    for (int o = 128; o; o >>= 1) { if (tid < o) red[tid] += red[tid + o]; __syncthreads(); }
    if (tid == 0) s_mean = red[0] / cols;
    __syncthreads();
    const float m = s_mean;

    float s2 = 0.f;
    for (int i = tid; i < cols; i += 256) {
        float v = x[i] + (r ? r[i] : 0.f) - m;
        s2 += v * v;
    }
    red[tid] = s2; __syncthreads();
    for (int o = 128; o; o >>= 1) { if (tid < o) red[tid] += red[tid + o]; __syncthreads(); }
    if (tid == 0) s_rstd = rsqrtf(red[0] / cols + 1e-5f);
    __syncthreads();
    const float rs = s_rstd;

    float* y = Y + (size_t)row * cols;
    for (int i = tid; i < cols; i += 256) {
        float v = x[i] + (r ? r[i] : 0.f);
        y[i] = (v - m) * rs * g[i] + b[i];
    }
}

// ---------------- concat img||txt -------------------------------------------------
__global__ void concat_kernel(const float* __restrict__ img, const float* __restrict__ txt,
                              float* __restrict__ cat)
{
    int idx = blockIdx.x * blockDim.x + threadIdx.x;
    if (idx >= BATCH * DMH) return;
    int b = idx >> 10, c = idx & 1023;
    cat[idx] = (c < DIMF) ? img[b*DIMF + c] : txt[b*DIMF + c - DIMF];
}

// ---------------- gate logits + softmax + gated concat into x --------------------
__global__ __launch_bounds__(256) void gate_finalize(
    const float* __restrict__ h2, const float* __restrict__ w3, const float* __restrict__ b3,
    const float* __restrict__ img, const float* __restrict__ txt,
    float* __restrict__ gate_out, float* __restrict__ x_out)
{
    const int b = blockIdx.x;
    const int tid = threadIdx.x;
    __shared__ float r0[256], r1[256];
    __shared__ float gs[2];
    float h = h2[b*256 + tid];
    r0[tid] = h * w3[tid];
    r1[tid] = h * w3[256 + tid];
    __syncthreads();
    for (int o = 128; o; o >>= 1) {
        if (tid < o) { r0[tid] += r0[tid + o]; r1[tid] += r1[tid + o]; }
        __syncthreads();
    }
    if (tid == 0) {
        float l0 = r0[0] + b3[0], l1 = r1[0] + b3[1];
        float mx = fmaxf(l0, l1);
        float e0 = expf(l0 - mx), e1 = expf(l1 - mx);
        float inv = 1.f / (e0 + e1);
        gs[0] = e0 * inv; gs[1] = e1 * inv;
        gate_out[b*2 + 0] = gs[0]; gate_out[b*2 + 1] = gs[1];
    }
    __syncthreads();
    float g0 = gs[0], g1 = gs[1];
    for (int c = tid; c < DMH; c += 256)
        x_out[b*DMH + c] = (c < DIMF) ? g0 * img[b*DIMF + c] : g1 * txt[b*DIMF + c - DIMF];
}

// ---------------- conv (L=1 -> scalar) + silu ------------------------------------
__global__ void conv_silu_kernel(const float* __restrict__ xz, const float* __restrict__ cw,
                                 const float* __restrict__ cb, float* __restrict__ xc)
{
    int idx = blockIdx.x * blockDim.x + threadIdx.x;
    if (idx >= BATCH * DIH) return;
    int b = idx >> 11, d = idx & (DIH - 1);
    float v = xz[(size_t)b * 2*DIH + d] * cw[d*4 + 3] + cb[d];
    xc[idx] = v / (1.f + __expf(-v));
}

// ---------------- collapsed SSM: y = (softplus(dpre)*xc*dot(B,C) + xc*D)*silu(z) --
__global__ __launch_bounds__(256) void y_kernel(
    const float* __restrict__ dpre, const float* __restrict__ xc,
    const float* __restrict__ xz, const float* __restrict__ dbc,
    const float* __restrict__ Dp, float* __restrict__ y)
{
    const int b = blockIdx.x;
    const float* row = dbc + b*96;
    float bc = 0.f;
#pragma unroll
    for (int s = 0; s < DSH; s++) bc += row[DTRH + s] * row[DTRH + DSH + s];
    for (int d = threadIdx.x; d < DIH; d += 256) {
        float dp = dpre[(size_t)b*DIH + d];
        float delta = (dp > 20.f) ? dp : log1pf(__expf(dp));
        float xcv = xc[(size_t)b*DIH + d];
        float zv = xz[(size_t)b*2*DIH + DIH + d];
        float silz = zv / (1.f + __expf(-zv));
        y[(size_t)b*DIH + d] = (delta * xcv * bc + xcv * Dp[d]) * silz;
    }
}

// ---------------- host-side helpers ----------------------------------------------
static inline void gemm(const float* A, int lda, const float* W, const float* bias,
                        float* C, int M, int N, int K, int epi)
{
    dim3 grid((N + BN - 1) / BN, M / BM);
    gemm_nt<<<grid, 256>>>(A, lda, W, bias, C, N, K, epi);
}

static inline float* sym(const void* s)
{
    void* p = nullptr;
    cudaGetSymbolAddress(&p, s);
    return (float*)p;
}

extern "C" void kernel_launch(void* const* d_in, const int* in_sizes, int n_in,
                              void* d_out, int out_size)
{
    const float* image   = (const float*)d_in[0];
    const float* text    = (const float*)d_in[1];
    const float* img_w   = (const float*)d_in[2];
    const float* img_b   = (const float*)d_in[3];
    const float* img_g   = (const float*)d_in[4];
    const float* img_bt  = (const float*)d_in[5];
    const float* txt_w   = (const float*)d_in[6];
    const float* txt_b   = (const float*)d_in[7];
    const float* txt_g   = (const float*)d_in[8];
    const float* txt_bt  = (const float*)d_in[9];
    const float* gate_w1 = (const float*)d_in[10];
    const float* gate_b1 = (const float*)d_in[11];
    const float* gate_w2 = (const float*)d_in[12];
    const float* gate_b2 = (const float*)d_in[13];
    const float* gate_w3 = (const float*)d_in[14];
    const float* gate_b3 = (const float*)d_in[15];
    const float* in_proj = (const float*)d_in[16];
    const float* conv_w  = (const float*)d_in[17];
    const float* conv_b  = (const float*)d_in[18];
    const float* x_proj  = (const float*)d_in[19];
    const float* dt_w    = (const float*)d_in[20];
    const float* dt_b    = (const float*)d_in[21];
    /* d_in[22] = A_log : dead (L=1, h0=0) */
    const float* D_par   = (const float*)d_in[23];
    const float* out_w   = (const float*)d_in[24];
    const float* mn_g    = (const float*)d_in[25];
    const float* mn_b    = (const float*)d_in[26];
    const float* fc_w    = (const float*)d_in[27];
    const float* fc_b    = (const float*)d_in[28];
    const float* fin_g   = (const float*)d_in[29];
    const float* fin_b   = (const float*)d_in[30];

    float* out = (float*)d_out;

    float* f0   = sym(g_f0);   float* f1  = sym(g_f1);
    float* t0   = sym(g_t0);   float* t1  = sym(g_t1);
    float* cat  = sym(g_cat);  float* h1  = sym(g_h1);  float* h2 = sym(g_h2);
    float* x    = sym(g_x);    float* xz  = sym(g_xz);  float* xc = sym(g_xc);
    float* dbc  = sym(g_dbc);  float* dpre= sym(g_dpre);
    float* y    = sym(g_y);    float* mo  = sym(g_mo);  float* fc = sym(g_fc);

    const int fused_elems = BATCH * 256;               // 262144
    float* gate_out = (out_size >= fused_elems + BATCH*2) ? (out + fused_elems)
                                                          : sym(g_gate_dummy);

    // ---- alignment towers (3x Linear+ReLU+LN each) ----
    const float* a_img = image;
    const float* a_txt = text;
    for (int i = 0; i < 3; i++) {
        gemm(a_img, DIMF, img_w + (size_t)i*DIMF*DIMF, img_b + i*DIMF, f1, BATCH, DIMF, DIMF, 1);
        ln_kernel<<<BATCH, 256>>>(f1, nullptr, img_g + i*DIMF, img_bt + i*DIMF, f0, DIMF);
        gemm(a_txt, DIMF, txt_w + (size_t)i*DIMF*DIMF, txt_b + i*DIMF, t1, BATCH, DIMF, DIMF, 1);
        ln_kernel<<<BATCH, 256>>>(t1, nullptr, txt_g + i*DIMF, txt_bt + i*DIMF, t0, DIMF);
        a_img = f0; a_txt = t0;
    }

    // ---- gating MLP ----
    concat_kernel<<<(BATCH*DMH + 255)/256, 256>>>(f0, t0, cat);
    gemm(cat, DMH, gate_w1, gate_b1, h1, BATCH, DIMF, DMH, 1);
    gemm(h1, DIMF, gate_w2, gate_b2, h2, BATCH, 256, DIMF, 1);
    gate_finalize<<<BATCH, 256>>>(h2, gate_w3, gate_b3, f0, t0, gate_out, x);

    // ---- 3 Mamba layers (L=1, SSM collapsed) ----
    for (int i = 0; i < 3; i++) {
        gemm(x, DMH, in_proj + (size_t)i*2*DIH*DMH, nullptr, xz, BATCH, 2*DIH, DMH, 0);
        conv_silu_kernel<<<(BATCH*DIH + 255)/256, 256>>>(
            xz, conv_w + (size_t)i*DIH*4, conv_b + (size_t)i*DIH, xc);
        gemm(xc, DIH, x_proj + (size_t)i*96*DIH, nullptr, dbc, BATCH, 96, DIH, 0);
        gemm(dbc, 96, dt_w + (size_t)i*DIH*DTRH, dt_b + (size_t)i*DIH, dpre, BATCH, DIH, DTRH, 0);
        y_kernel<<<BATCH, 256>>>(dpre, xc, xz, dbc, D_par + (size_t)i*DIH, y);
        gemm(y, DIH, out_w + (size_t)i*DMH*DIH, nullptr, mo, BATCH, DMH, DIH, 0);
        ln_kernel<<<BATCH, 256>>>(mo, x, mn_g + (size_t)i*DMH, mn_b + (size_t)i*DMH, x, DMH);
    }

    // ---- head ----
    gemm(x, DMH, fc_w, fc_b, fc, BATCH, 256, DMH, 0);
    ln_kernel<<<BATCH, 256>>>(fc, nullptr, fin_g, fin_b, out, 256);
}

// round 7
// speedup vs baseline: 2.3069x; 2.3069x over previous
#include <cuda_runtime.h>
#include <cuda_bf16.h>
#include <cstdint>
#include <math.h>

#define BATCH 1024
#define DIMF  512
#define DMH   1024   // 2*DIM
#define DIH   2048   // 2*DM
#define DTRH  64     // DM/16
#define DSH   16

// ================= scratch (device globals; no allocation allowed) ================
__device__ __align__(256) float g_f0[BATCH*DIMF], g_f1[BATCH*DIMF];
__device__ __align__(256) float g_t0[BATCH*DIMF], g_t1[BATCH*DIMF];
__device__ __align__(256) float g_h1[BATCH*DIMF];
__device__ __align__(256) float g_h2[BATCH*256];
__device__ __align__(256) float g_x[BATCH*DMH];
__device__ __align__(256) float g_xz[BATCH*2*DIH];
__device__ __align__(256) float g_xc[BATCH*DIH];
__device__ __align__(256) float g_dbc[BATCH*96];
__device__ __align__(256) float g_dpre[BATCH*DIH];
__device__ __align__(256) float g_y[BATCH*DIH];
__device__ __align__(256) float g_mo[BATCH*DMH];
__device__ __align__(256) float g_fc[BATCH*256];
__device__ __align__(256) float g_cat[BATCH*DMH];
__device__ __align__(256) float g_gate_dummy[BATCH*2];

// ================= HMMA GEMM ======================================================
// C[M,N] = epi(A[M,K] @ W[N,K]^T + bias). fp32 in/out.
// bf16 hi/lo split on tensor cores (3 passes), fp32 accumulate.
// Tile: 128x64x32, 8 warps (warp tile 32x32). M%128==0, K%32==0, N even (guarded).

#define SAST 40          // smem row stride in halves (32 + 8 pad -> 20 banks, conflict-free)

#define MMA_BF16(c, a, b) \
    asm volatile("mma.sync.aligned.m16n8k16.row.col.f32.bf16.bf16.f32 " \
        "{%0,%1,%2,%3}, {%4,%5,%6,%7}, {%8,%9}, {%0,%1,%2,%3};" \
        : "+f"((c)[0]), "+f"((c)[1]), "+f"((c)[2]), "+f"((c)[3]) \
        : "r"((a)[0]), "r"((a)[1]), "r"((a)[2]), "r"((a)[3]), \
          "r"((b)[0]), "r"((b)[1]))

__device__ __forceinline__ uint32_t pack_bf2(float a, float b) {
    __nv_bfloat162 t = __floats2bfloat162_rn(a, b);
    return *reinterpret_cast<uint32_t*>(&t);
}
__device__ __forceinline__ void split4(float4 v, uint2& hi, uint2& lo) {
    float hx = __bfloat162float(__float2bfloat16_rn(v.x));
    float hy = __bfloat162float(__float2bfloat16_rn(v.y));
    float hz = __bfloat162float(__float2bfloat16_rn(v.z));
    float hw = __bfloat162float(__float2bfloat16_rn(v.w));
    hi.x = pack_bf2(hx, hy);          hi.y = pack_bf2(hz, hw);
    lo.x = pack_bf2(v.x - hx, v.y - hy);
    lo.y = pack_bf2(v.z - hz, v.w - hw);
}

__global__ __launch_bounds__(256, 2) void gemm_mma(
    const float* __restrict__ A, int lda,
    const float* __restrict__ W,
    const float* __restrict__ bias,
    float* __restrict__ C, int N, int K, int epi)
{
    __shared__ __align__(16) __nv_bfloat16 sAh[128*SAST];
    __shared__ __align__(16) __nv_bfloat16 sAl[128*SAST];
    __shared__ __align__(16) __nv_bfloat16 sBh[64*SAST];
    __shared__ __align__(16) __nv_bfloat16 sBl[64*SAST];

    const int tid  = threadIdx.x;
    const int wid  = tid >> 5;
    const int lane = tid & 31;
    const int m0 = blockIdx.y << 7;
    const int n0 = blockIdx.x << 6;
    const int wm = (wid >> 1) << 5;     // 0,32,64,96
    const int wn = (wid & 1)  << 5;     // 0,32
    const int g  = lane >> 2;           // 0..7
    const int th = lane & 3;            // 0..3

    // gmem load geometry: 8 threads per 32-float row
    const int lr = tid >> 3;            // 0..31
    const int lc = (tid & 7) << 2;      // 0,4,...,28

    float acc[2][4][4];
#pragma unroll
    for (int mt = 0; mt < 2; mt++)
#pragma unroll
        for (int nt = 0; nt < 4; nt++)
#pragma unroll
            for (int r = 0; r < 4; r++) acc[mt][nt][r] = 0.f;

    const int nchunk = K >> 5;
    float4 aq[4], bq[2];

    // ---- prologue: load chunk 0 ----
#pragma unroll
    for (int i = 0; i < 4; i++)
        aq[i] = *(const float4*)(A + (size_t)(m0 + lr + 32*i) * lda + lc);
#pragma unroll
    for (int i = 0; i < 2; i++) {
        int row = lr + 32*i;
        bq[i] = (n0 + row < N) ? *(const float4*)(W + (size_t)(n0 + row) * K + lc)
                               : make_float4(0.f, 0.f, 0.f, 0.f);
    }
#pragma unroll
    for (int i = 0; i < 4; i++) {
        int row = lr + 32*i;
        uint2 hi, lo; split4(aq[i], hi, lo);
        *(uint2*)(&sAh[row*SAST + lc]) = hi;
        *(uint2*)(&sAl[row*SAST + lc]) = lo;
    }
#pragma unroll
    for (int i = 0; i < 2; i++) {
        int row = lr + 32*i;
        uint2 hi, lo; split4(bq[i], hi, lo);
        *(uint2*)(&sBh[row*SAST + lc]) = hi;
        *(uint2*)(&sBl[row*SAST + lc]) = lo;
    }
    __syncthreads();

    for (int kt = 0; kt < nchunk; kt++) {
        const bool more = (kt + 1) < nchunk;
        if (more) {
            const int k0 = (kt + 1) << 5;
#pragma unroll
            for (int i = 0; i < 4; i++)
                aq[i] = *(const float4*)(A + (size_t)(m0 + lr + 32*i) * lda + k0 + lc);
#pragma unroll
            for (int i = 0; i < 2; i++) {
                int row = lr + 32*i;
                bq[i] = (n0 + row < N)
                      ? *(const float4*)(W + (size_t)(n0 + row) * K + k0 + lc)
                      : make_float4(0.f, 0.f, 0.f, 0.f);
            }
        }

        // ---- compute 2 k-steps of 16 from smem ----
#pragma unroll
        for (int ks = 0; ks < 2; ks++) {
            const int kb = ks << 4;
            uint32_t ah[2][4], al[2][4], bx[4][2];
#pragma unroll
            for (int mt = 0; mt < 2; mt++) {
                const __nv_bfloat16* p = &sAh[(wm + mt*16 + g)*SAST + kb + th*2];
                ah[mt][0] = *(const uint32_t*)p;
                ah[mt][1] = *(const uint32_t*)(p + 8*SAST);
                ah[mt][2] = *(const uint32_t*)(p + 8);
                ah[mt][3] = *(const uint32_t*)(p + 8*SAST + 8);
                const __nv_bfloat16* q = &sAl[(wm + mt*16 + g)*SAST + kb + th*2];
                al[mt][0] = *(const uint32_t*)q;
                al[mt][1] = *(const uint32_t*)(q + 8*SAST);
                al[mt][2] = *(const uint32_t*)(q + 8);
                al[mt][3] = *(const uint32_t*)(q + 8*SAST + 8);
            }
            // pass 1+2: B_hi with A_hi and A_lo
#pragma unroll
            for (int nt = 0; nt < 4; nt++) {
                const __nv_bfloat16* p = &sBh[(wn + nt*8 + g)*SAST + kb + th*2];
                bx[nt][0] = *(const uint32_t*)p;
                bx[nt][1] = *(const uint32_t*)(p + 8);
            }
#pragma unroll
            for (int mt = 0; mt < 2; mt++)
#pragma unroll
                for (int nt = 0; nt < 4; nt++) MMA_BF16(acc[mt][nt], ah[mt], bx[nt]);
#pragma unroll
            for (int mt = 0; mt < 2; mt++)
#pragma unroll
                for (int nt = 0; nt < 4; nt++) MMA_BF16(acc[mt][nt], al[mt], bx[nt]);
            // pass 3: A_hi with B_lo
#pragma unroll
            for (int nt = 0; nt < 4; nt++) {
                const __nv_bfloat16* p = &sBl[(wn + nt*8 + g)*SAST + kb + th*2];
                bx[nt][0] = *(const uint32_t*)p;
                bx[nt][1] = *(const uint32_t*)(p + 8);
            }
#pragma unroll
            for (int mt = 0; mt < 2; mt++)
#pragma unroll
                for (int nt = 0; nt < 4; nt++) MMA_BF16(acc[mt][nt], ah[mt], bx[nt]);
        }
        __syncthreads();

        if (more) {
#pragma unroll
            for (int i = 0; i < 4; i++) {
                int row = lr + 32*i;
                uint2 hi, lo; split4(aq[i], hi, lo);
                *(uint2*)(&sAh[row*SAST + lc]) = hi;
                *(uint2*)(&sAl[row*SAST + lc]) = lo;
            }
#pragma unroll
            for (int i = 0; i < 2; i++) {
                int row = lr + 32*i;
                uint2 hi, lo; split4(bq[i], hi, lo);
                *(uint2*)(&sBh[row*SAST + lc]) = hi;
                *(uint2*)(&sBl[row*SAST + lc]) = lo;
            }
            __syncthreads();
        }
    }

    // ---- epilogue: direct stores, bias + optional ReLU ----
#pragma unroll
    for (int mt = 0; mt < 2; mt++) {
        const int r0 = m0 + wm + mt*16 + g;
#pragma unroll
        for (int nt = 0; nt < 4; nt++) {
            const int cb = n0 + wn + nt*8 + th*2;
            if (cb < N) {
                float bx = 0.f, by = 0.f;
                if (bias) { bx = bias[cb]; by = bias[cb + 1]; }
                float2 v0 = make_float2(acc[mt][nt][0] + bx, acc[mt][nt][1] + by);
                float2 v1 = make_float2(acc[mt][nt][2] + bx, acc[mt][nt][3] + by);
                if (epi) {
                    v0.x = fmaxf(v0.x, 0.f); v0.y = fmaxf(v0.y, 0.f);
                    v1.x = fmaxf(v1.x, 0.f); v1.y = fmaxf(v1.y, 0.f);
                }
                *(float2*)&C[(size_t)r0 * N + cb] = v0;
                *(float2*)&C[(size_t)(r0 + 8) * N + cb] = v1;
            }
        }
    }
}

// ================= LayerNorm: one warp per row, float4 + shuffles ================
__global__ __launch_bounds__(256) void ln_warp(
    const float* __restrict__ X, const float* __restrict__ R,
    const float* __restrict__ g, const float* __restrict__ b,
    float* __restrict__ Y, int cols)
{
    const int row = blockIdx.x * 8 + (threadIdx.x >> 5);
    const int lane = threadIdx.x & 31;
    const int n4 = cols >> 2;
    const float4* x4 = (const float4*)(X + (size_t)row * cols);
    const float4* r4 = R ? (const float4*)(R + (size_t)row * cols) : nullptr;

    float s = 0.f, q = 0.f;
    for (int i = lane; i < n4; i += 32) {
        float4 v = x4[i];
        if (r4) { float4 rr = r4[i]; v.x += rr.x; v.y += rr.y; v.z += rr.z; v.w += rr.w; }
        s += v.x + v.y + v.z + v.w;
        q += v.x * v.x + v.y * v.y + v.z * v.z + v.w * v.w;
    }
#pragma unroll
    for (int o = 16; o; o >>= 1) {
        s += __shfl_xor_sync(0xFFFFFFFFu, s, o);
        q += __shfl_xor_sync(0xFFFFFFFFu, q, o);
    }
    const float m = s / cols;
    const float rs = rsqrtf(q / cols - m * m + 1e-5f);

    float4* y4 = (float4*)(Y + (size_t)row * cols);
    const float4* g4 = (const float4*)g;
    const float4* b4 = (const float4*)b;
    for (int i = lane; i < n4; i += 32) {
        float4 v = x4[i];
        if (r4) { float4 rr = r4[i]; v.x += rr.x; v.y += rr.y; v.z += rr.z; v.w += rr.w; }
        float4 gg = g4[i], bb = b4[i];
        v.x = (v.x - m) * rs * gg.x + bb.x;
        v.y = (v.y - m) * rs * gg.y + bb.y;
        v.z = (v.z - m) * rs * gg.z + bb.z;
        v.w = (v.w - m) * rs * gg.w + bb.w;
        y4[i] = v;
    }
}

// ================= concat img||txt ===============================================
__global__ void concat_kernel(const float* __restrict__ img, const float* __restrict__ txt,
                              float* __restrict__ cat)
{
    int idx = blockIdx.x * blockDim.x + threadIdx.x;
    if (idx >= BATCH * DMH) return;
    int b = idx >> 10, c = idx & 1023;
    cat[idx] = (c < DIMF) ? img[b * DIMF + c] : txt[b * DIMF + c - DIMF];
}

// ================= gate logits + softmax + gated concat ==========================
__global__ __launch_bounds__(256) void gate_finalize(
    const float* __restrict__ h2, const float* __restrict__ w3, const float* __restrict__ b3,
    const float* __restrict__ img, const float* __restrict__ txt,
    float* __restrict__ gate_out, float* __restrict__ x_out)
{
    const int b = blockIdx.x;
    const int tid = threadIdx.x;
    __shared__ float r0[256], r1[256];
    __shared__ float gs[2];
    float h = h2[b * 256 + tid];
    r0[tid] = h * w3[tid];
    r1[tid] = h * w3[256 + tid];
    __syncthreads();
    for (int o = 128; o; o >>= 1) {
        if (tid < o) { r0[tid] += r0[tid + o]; r1[tid] += r1[tid + o]; }
        __syncthreads();
    }
    if (tid == 0) {
        float l0 = r0[0] + b3[0], l1 = r1[0] + b3[1];
        float mx = fmaxf(l0, l1);
        float e0 = expf(l0 - mx), e1 = expf(l1 - mx);
        float inv = 1.f / (e0 + e1);
        gs[0] = e0 * inv; gs[1] = e1 * inv;
        gate_out[b * 2 + 0] = gs[0]; gate_out[b * 2 + 1] = gs[1];
    }
    __syncthreads();
    float g0 = gs[0], g1 = gs[1];
    for (int c = tid; c < DMH; c += 256)
        x_out[b * DMH + c] = (c < DIMF) ? g0 * img[b * DIMF + c] : g1 * txt[b * DIMF + c - DIMF];
}

// ================= conv (L=1 -> scalar) + silu ===================================
__global__ void conv_silu_kernel(const float* __restrict__ xz, const float* __restrict__ cw,
                                 const float* __restrict__ cb, float* __restrict__ xc)
{
    int idx = blockIdx.x * blockDim.x + threadIdx.x;
    if (idx >= BATCH * DIH) return;
    int b = idx >> 11, d = idx & (DIH - 1);
    float v = xz[(size_t)b * 2 * DIH + d] * cw[d * 4 + 3] + cb[d];
    xc[idx] = v / (1.f + __expf(-v));
}

// ============ collapsed SSM: y = (softplus(dpre)*xc*dot(B,C) + xc*D)*silu(z) =====
__global__ __launch_bounds__(256) void y_kernel(
    const float* __restrict__ dpre, const float* __restrict__ xc,
    const float* __restrict__ xz, const float* __restrict__ dbc,
    const float* __restrict__ Dp, float* __restrict__ y)
{
    const int b = blockIdx.x;
    const float* row = dbc + b * 96;
    float bc = 0.f;
#pragma unroll
    for (int s = 0; s < DSH; s++) bc += row[DTRH + s] * row[DTRH + DSH + s];
    for (int d = threadIdx.x; d < DIH; d += 256) {
        float dp = dpre[(size_t)b * DIH + d];
        float delta = (dp > 20.f) ? dp : log1pf(__expf(dp));
        float xcv = xc[(size_t)b * DIH + d];
        float zv = xz[(size_t)b * 2 * DIH + DIH + d];
        float silz = zv / (1.f + __expf(-zv));
        y[(size_t)b * DIH + d] = (delta * xcv * bc + xcv * Dp[d]) * silz;
    }
}

// ================= host side ======================================================
static inline void gemm(const float* A, int lda, const float* W, const float* bias,
                        float* C, int M, int N, int K, int epi)
{
    dim3 grid((N + 63) / 64, M / 128);
    gemm_mma<<<grid, 256>>>(A, lda, W, bias, C, N, K, epi);
}

static inline float* sym(const void* s)
{
    void* p = nullptr;
    cudaGetSymbolAddress(&p, s);
    return (float*)p;
}

extern "C" void kernel_launch(void* const* d_in, const int* in_sizes, int n_in,
                              void* d_out, int out_size)
{
    const float* image   = (const float*)d_in[0];
    const float* text    = (const float*)d_in[1];
    const float* img_w   = (const float*)d_in[2];
    const float* img_b   = (const float*)d_in[3];
    const float* img_g   = (const float*)d_in[4];
    const float* img_bt  = (const float*)d_in[5];
    const float* txt_w   = (const float*)d_in[6];
    const float* txt_b   = (const float*)d_in[7];
    const float* txt_g   = (const float*)d_in[8];
    const float* txt_bt  = (const float*)d_in[9];
    const float* gate_w1 = (const float*)d_in[10];
    const float* gate_b1 = (const float*)d_in[11];
    const float* gate_w2 = (const float*)d_in[12];
    const float* gate_b2 = (const float*)d_in[13];
    const float* gate_w3 = (const float*)d_in[14];
    const float* gate_b3 = (const float*)d_in[15];
    const float* in_proj = (const float*)d_in[16];
    const float* conv_w  = (const float*)d_in[17];
    const float* conv_b  = (const float*)d_in[18];
    const float* x_proj  = (const float*)d_in[19];
    const float* dt_w    = (const float*)d_in[20];
    const float* dt_b    = (const float*)d_in[21];
    /* d_in[22] = A_log : dead (L=1, h0=0) */
    const float* D_par   = (const float*)d_in[23];
    const float* out_w   = (const float*)d_in[24];
    const float* mn_g    = (const float*)d_in[25];
    const float* mn_b    = (const float*)d_in[26];
    const float* fc_w    = (const float*)d_in[27];
    const float* fc_b    = (const float*)d_in[28];
    const float* fin_g   = (const float*)d_in[29];
    const float* fin_b   = (const float*)d_in[30];

    float* out = (float*)d_out;

    float* f0  = sym(g_f0);  float* f1  = sym(g_f1);
    float* t0  = sym(g_t0);  float* t1  = sym(g_t1);
    float* cat = sym(g_cat); float* h1  = sym(g_h1); float* h2 = sym(g_h2);
    float* x   = sym(g_x);   float* xz  = sym(g_xz); float* xc = sym(g_xc);
    float* dbc = sym(g_dbc); float* dpre = sym(g_dpre);
    float* y   = sym(g_y);   float* mo  = sym(g_mo); float* fc = sym(g_fc);

    const int fused_elems = BATCH * 256;
    float* gate_out = (out_size >= fused_elems + BATCH * 2) ? (out + fused_elems)
                                                            : sym(g_gate_dummy);

    // ---- alignment towers (3x Linear+ReLU+LN each) ----
    const float* a_img = image;
    const float* a_txt = text;
    for (int i = 0; i < 3; i++) {
        gemm(a_img, DIMF, img_w + (size_t)i * DIMF * DIMF, img_b + i * DIMF, f1, BATCH, DIMF, DIMF, 1);
        ln_warp<<<BATCH / 8, 256>>>(f1, nullptr, img_g + i * DIMF, img_bt + i * DIMF, f0, DIMF);
        gemm(a_txt, DIMF, txt_w + (size_t)i * DIMF * DIMF, txt_b + i * DIMF, t1, BATCH, DIMF, DIMF, 1);
        ln_warp<<<BATCH / 8, 256>>>(t1, nullptr, txt_g + i * DIMF, txt_bt + i * DIMF, t0, DIMF);
        a_img = f0; a_txt = t0;
    }

    // ---- gating MLP ----
    concat_kernel<<<(BATCH * DMH + 255) / 256, 256>>>(f0, t0, cat);
    gemm(cat, DMH, gate_w1, gate_b1, h1, BATCH, DIMF, DMH, 1);
    gemm(h1, DIMF, gate_w2, gate_b2, h2, BATCH, 256, DIMF, 1);
    gate_finalize<<<BATCH, 256>>>(h2, gate_w3, gate_b3, f0, t0, gate_out, x);

    // ---- 3 Mamba layers (L=1, SSM collapsed) ----
    for (int i = 0; i < 3; i++) {
        gemm(x, DMH, in_proj + (size_t)i * 2 * DIH * DMH, nullptr, xz, BATCH, 2 * DIH, DMH, 0);
        conv_silu_kernel<<<(BATCH * DIH + 255) / 256, 256>>>(
            xz, conv_w + (size_t)i * DIH * 4, conv_b + (size_t)i * DIH, xc);
        gemm(xc, DIH, x_proj + (size_t)i * 96 * DIH, nullptr, dbc, BATCH, 96, DIH, 0);
        gemm(dbc, 96, dt_w + (size_t)i * DIH * DTRH, dt_b + (size_t)i * DIH, dpre, BATCH, DIH, DTRH, 0);
        y_kernel<<<BATCH, 256>>>(dpre, xc, xz, dbc, D_par + (size_t)i * DIH, y);
        gemm(y, DIH, out_w + (size_t)i * DMH * DIH, nullptr, mo, BATCH, DMH, DIH, 0);
        ln_warp<<<BATCH / 8, 256>>>(mo, x, mn_g + (size_t)i * DMH, mn_b + (size_t)i * DMH, x, DMH);
    }

    // ---- head ----
    gemm(x, DMH, fc_w, fc_b, fc, BATCH, 256, DMH, 0);
    ln_warp<<<BATCH / 8, 256>>>(fc, nullptr, fin_g, fin_b, out, 256);
}

// round 10
// speedup vs baseline: 3.0919x; 1.3403x over previous
#include <cuda_runtime.h>
#include <cuda_bf16.h>
#include <cuda_fp16.h>
#include <cstdint>
#include <math.h>

#define BATCH 1024
#define DIMF  512
#define DMH   1024   // 2*DIM
#define DIH   2048   // 2*DM
#define DTRH  64     // DM/16
#define DSH   16

// ================= scratch (device globals; no allocation allowed) ================
__device__ __align__(256) float g_f0[BATCH*DIMF], g_f1[BATCH*DIMF];
__device__ __align__(256) float g_t0[BATCH*DIMF], g_t1[BATCH*DIMF];
__device__ __align__(256) float g_h1[BATCH*DIMF];
__device__ __align__(256) float g_h2[BATCH*256];
__device__ __align__(256) float g_x[BATCH*DMH];
__device__ __align__(256) float g_xz[BATCH*2*DIH];
__device__ __align__(256) float g_xc[BATCH*DIH];
__device__ __align__(256) float g_dbc[BATCH*96];
__device__ __align__(256) float g_dpre[BATCH*DIH];
__device__ __align__(256) float g_y[BATCH*DIH];
__device__ __align__(256) float g_mo[BATCH*DMH];
__device__ __align__(256) float g_fc[BATCH*256];
__device__ __align__(256) float g_cat[BATCH*DMH];
__device__ __align__(256) float g_gate_dummy[BATCH*2];

// ================= HMMA GEMM (fp16 single-pass, ldmatrix, double-buffered) ========
// C[M,N] = epi(A[M,K] @ W[N,K]^T + bias). fp32 in/out, fp16 on tensor cores,
// fp32 accumulate. Tile 128x64x32, 8 warps (warp tile 32x32).
// M%128==0, K%32==0, N guarded.

#define SAST 40          // smem row stride in halves (80B: 16B-aligned rows, LDSM conflict-free)

#define MMA_F16(c, a, b) \
    asm volatile("mma.sync.aligned.m16n8k16.row.col.f32.f16.f16.f32 " \
        "{%0,%1,%2,%3}, {%4,%5,%6,%7}, {%8,%9}, {%0,%1,%2,%3};" \
        : "+f"((c)[0]), "+f"((c)[1]), "+f"((c)[2]), "+f"((c)[3]) \
        : "r"((a)[0]), "r"((a)[1]), "r"((a)[2]), "r"((a)[3]), \
          "r"((b)[0]), "r"((b)[1]))

#define LDSM_X4(r0, r1, r2, r3, saddr) \
    asm volatile("ldmatrix.sync.aligned.m8n8.x4.shared.b16 {%0,%1,%2,%3}, [%4];" \
        : "=r"(r0), "=r"(r1), "=r"(r2), "=r"(r3) : "r"(saddr))

__device__ __forceinline__ uint2 f4_to_h4(float4 v) {
    __half2 p0 = __floats2half2_rn(v.x, v.y);
    __half2 p1 = __floats2half2_rn(v.z, v.w);
    uint2 r;
    r.x = *reinterpret_cast<uint32_t*>(&p0);
    r.y = *reinterpret_cast<uint32_t*>(&p1);
    return r;
}

__global__ __launch_bounds__(256, 2) void gemm_mma(
    const float* __restrict__ A, int lda,
    const float* __restrict__ W,
    const float* __restrict__ bias,
    float* __restrict__ C, int N, int K, int epi)
{
    __shared__ __align__(16) __half sA[2][128 * SAST];
    __shared__ __align__(16) __half sB[2][64 * SAST];

    const int tid  = threadIdx.x;
    const int wid  = tid >> 5;
    const int lane = tid & 31;
    const int m0 = blockIdx.y << 7;
    const int n0 = blockIdx.x << 6;
    const int wm = (wid >> 1) << 5;     // 0,32,64,96
    const int wn = (wid & 1)  << 5;     // 0,32
    const int g  = lane >> 2;           // 0..7
    const int th = lane & 3;            // 0..3

    // gmem load geometry: 8 threads per 32-float row
    const int lr = tid >> 3;            // 0..31
    const int lc = (tid & 7) << 2;      // 0,4,...,28

    // ldmatrix lane addressing
    const int a_row = lane & 15;               // row within m16 tile
    const int a_koff = (lane >> 4) << 3;       // 0 or 8
    const int b_row = (lane & 7) + ((lane >> 4) << 3);  // n row within n16 pair
    const int b_koff = lane & 8;               // 0 or 8

    float acc[2][4][4];
#pragma unroll
    for (int mt = 0; mt < 2; mt++)
#pragma unroll
        for (int nt = 0; nt < 4; nt++)
#pragma unroll
            for (int r = 0; r < 4; r++) acc[mt][nt][r] = 0.f;

    const int nchunk = K >> 5;
    float4 aq[4], bq[2];

    // ---- prologue: load + convert + store chunk 0 into buf 0 ----
#pragma unroll
    for (int i = 0; i < 4; i++)
        aq[i] = *(const float4*)(A + (size_t)(m0 + lr + 32*i) * lda + lc);
#pragma unroll
    for (int i = 0; i < 2; i++) {
        int row = lr + 32*i;
        bq[i] = (n0 + row < N) ? *(const float4*)(W + (size_t)(n0 + row) * K + lc)
                               : make_float4(0.f, 0.f, 0.f, 0.f);
    }
#pragma unroll
    for (int i = 0; i < 4; i++)
        *(uint2*)(&sA[0][(lr + 32*i) * SAST + lc]) = f4_to_h4(aq[i]);
#pragma unroll
    for (int i = 0; i < 2; i++)
        *(uint2*)(&sB[0][(lr + 32*i) * SAST + lc]) = f4_to_h4(bq[i]);
    __syncthreads();

    for (int kt = 0; kt < nchunk; kt++) {
        const int cur = kt & 1;
        const bool more = (kt + 1) < nchunk;

        // ---- prefetch next chunk from gmem (overlaps MMA below) ----
        if (more) {
            const int k0 = (kt + 1) << 5;
#pragma unroll
            for (int i = 0; i < 4; i++)
                aq[i] = *(const float4*)(A + (size_t)(m0 + lr + 32*i) * lda + k0 + lc);
#pragma unroll
            for (int i = 0; i < 2; i++) {
                int row = lr + 32*i;
                bq[i] = (n0 + row < N)
                      ? *(const float4*)(W + (size_t)(n0 + row) * K + k0 + lc)
                      : make_float4(0.f, 0.f, 0.f, 0.f);
            }
        }

        // ---- compute: 2 k16 steps via ldmatrix + mma ----
#pragma unroll
        for (int ks = 0; ks < 2; ks++) {
            const int kb = ks << 4;
            uint32_t af[2][4], bf[4][2];
#pragma unroll
            for (int mt = 0; mt < 2; mt++) {
                uint32_t sa = (uint32_t)__cvta_generic_to_shared(
                    &sA[cur][(wm + mt*16 + a_row) * SAST + kb + a_koff]);
                LDSM_X4(af[mt][0], af[mt][1], af[mt][2], af[mt][3], sa);
            }
#pragma unroll
            for (int ntp = 0; ntp < 2; ntp++) {
                uint32_t sbN = (uint32_t)__cvta_generic_to_shared(
                    &sB[cur][(wn + ntp*16 + b_row) * SAST + kb + b_koff]);
                LDSM_X4(bf[2*ntp][0], bf[2*ntp][1], bf[2*ntp+1][0], bf[2*ntp+1][1], sbN);
            }
#pragma unroll
            for (int mt = 0; mt < 2; mt++)
#pragma unroll
                for (int nt = 0; nt < 4; nt++) MMA_F16(acc[mt][nt], af[mt], bf[nt]);
        }

        // ---- convert + store next chunk into the other buffer ----
        if (more) {
            const int nxt = cur ^ 1;
#pragma unroll
            for (int i = 0; i < 4; i++)
                *(uint2*)(&sA[nxt][(lr + 32*i) * SAST + lc]) = f4_to_h4(aq[i]);
#pragma unroll
            for (int i = 0; i < 2; i++)
                *(uint2*)(&sB[nxt][(lr + 32*i) * SAST + lc]) = f4_to_h4(bq[i]);
        }
        __syncthreads();
    }

    // ---- epilogue: direct stores, bias + optional ReLU ----
#pragma unroll
    for (int mt = 0; mt < 2; mt++) {
        const int r0 = m0 + wm + mt*16 + g;
#pragma unroll
        for (int nt = 0; nt < 4; nt++) {
            const int cb = n0 + wn + nt*8 + th*2;
            if (cb < N) {
                float bx = 0.f, by = 0.f;
                if (bias) { bx = bias[cb]; by = bias[cb + 1]; }
                float2 v0 = make_float2(acc[mt][nt][0] + bx, acc[mt][nt][1] + by);
                float2 v1 = make_float2(acc[mt][nt][2] + bx, acc[mt][nt][3] + by);
                if (epi) {
                    v0.x = fmaxf(v0.x, 0.f); v0.y = fmaxf(v0.y, 0.f);
                    v1.x = fmaxf(v1.x, 0.f); v1.y = fmaxf(v1.y, 0.f);
                }
                *(float2*)&C[(size_t)r0 * N + cb] = v0;
                *(float2*)&C[(size_t)(r0 + 8) * N + cb] = v1;
            }
        }
    }
}

// ================= LayerNorm: one warp per row, float4 + shuffles ================
__global__ __launch_bounds__(128) void ln_warp(
    const float* __restrict__ X, const float* __restrict__ R,
    const float* __restrict__ g, const float* __restrict__ b,
    float* __restrict__ Y, int cols)
{
    const int row = blockIdx.x * 4 + (threadIdx.x >> 5);
    const int lane = threadIdx.x & 31;
    const int n4 = cols >> 2;
    const float4* x4 = (const float4*)(X + (size_t)row * cols);
    const float4* r4 = R ? (const float4*)(R + (size_t)row * cols) : nullptr;

    float s = 0.f, q = 0.f;
    for (int i = lane; i < n4; i += 32) {
        float4 v = x4[i];
        if (r4) { float4 rr = r4[i]; v.x += rr.x; v.y += rr.y; v.z += rr.z; v.w += rr.w; }
        s += v.x + v.y + v.z + v.w;
        q += v.x * v.x + v.y * v.y + v.z * v.z + v.w * v.w;
    }
#pragma unroll
    for (int o = 16; o; o >>= 1) {
        s += __shfl_xor_sync(0xFFFFFFFFu, s, o);
        q += __shfl_xor_sync(0xFFFFFFFFu, q, o);
    }
    const float m = s / cols;
    const float rs = rsqrtf(q / cols - m * m + 1e-5f);

    float4* y4 = (float4*)(Y + (size_t)row * cols);
    const float4* g4 = (const float4*)g;
    const float4* b4 = (const float4*)b;
    for (int i = lane; i < n4; i += 32) {
        float4 v = x4[i];
        if (r4) { float4 rr = r4[i]; v.x += rr.x; v.y += rr.y; v.z += rr.z; v.w += rr.w; }
        float4 gg = g4[i], bb = b4[i];
        v.x = (v.x - m) * rs * gg.x + bb.x;
        v.y = (v.y - m) * rs * gg.y + bb.y;
        v.z = (v.z - m) * rs * gg.z + bb.z;
        v.w = (v.w - m) * rs * gg.w + bb.w;
        y4[i] = v;
    }
}

// ================= concat img||txt ===============================================
__global__ void concat_kernel(const float* __restrict__ img, const float* __restrict__ txt,
                              float* __restrict__ cat)
{
    int idx = blockIdx.x * blockDim.x + threadIdx.x;
    if (idx >= BATCH * DMH) return;
    int b = idx >> 10, c = idx & 1023;
    cat[idx] = (c < DIMF) ? img[b * DIMF + c] : txt[b * DIMF + c - DIMF];
}

// ================= gate logits + softmax + gated concat ==========================
__global__ __launch_bounds__(256) void gate_finalize(
    const float* __restrict__ h2, const float* __restrict__ w3, const float* __restrict__ b3,
    const float* __restrict__ img, const float* __restrict__ txt,
    float* __restrict__ gate_out, float* __restrict__ x_out)
{
    const int b = blockIdx.x;
    const int tid = threadIdx.x;
    __shared__ float r0[256], r1[256];
    __shared__ float gs[2];
    float h = h2[b * 256 + tid];
    r0[tid] = h * w3[tid];
    r1[tid] = h * w3[256 + tid];
    __syncthreads();
    for (int o = 128; o; o >>= 1) {
        if (tid < o) { r0[tid] += r0[tid + o]; r1[tid] += r1[tid + o]; }
        __syncthreads();
    }
    if (tid == 0) {
        float l0 = r0[0] + b3[0], l1 = r1[0] + b3[1];
        float mx = fmaxf(l0, l1);
        float e0 = expf(l0 - mx), e1 = expf(l1 - mx);
        float inv = 1.f / (e0 + e1);
        gs[0] = e0 * inv; gs[1] = e1 * inv;
        gate_out[b * 2 + 0] = gs[0]; gate_out[b * 2 + 1] = gs[1];
    }
    __syncthreads();
    float g0 = gs[0], g1 = gs[1];
    for (int c = tid; c < DMH; c += 256)
        x_out[b * DMH + c] = (c < DIMF) ? g0 * img[b * DIMF + c] : g1 * txt[b * DIMF + c - DIMF];
}

// ================= conv (L=1 -> scalar) + silu ===================================
__global__ void conv_silu_kernel(const float* __restrict__ xz, const float* __restrict__ cw,
                                 const float* __restrict__ cb, float* __restrict__ xc)
{
    int idx = blockIdx.x * blockDim.x + threadIdx.x;
    if (idx >= BATCH * DIH) return;
    int b = idx >> 11, d = idx & (DIH - 1);
    float v = xz[(size_t)b * 2 * DIH + d] * cw[d * 4 + 3] + cb[d];
    xc[idx] = v / (1.f + __expf(-v));
}

// ============ collapsed SSM: y = (softplus(dpre)*xc*dot(B,C) + xc*D)*silu(z) =====
__global__ __launch_bounds__(256) void y_kernel(
    const float* __restrict__ dpre, const float* __restrict__ xc,
    const float* __restrict__ xz, const float* __restrict__ dbc,
    const float* __restrict__ Dp, float* __restrict__ y)
{
    const int b = blockIdx.x;
    const float* row = dbc + b * 96;
    float bc = 0.f;
#pragma unroll
    for (int s = 0; s < DSH; s++) bc += row[DTRH + s] * row[DTRH + DSH + s];
    for (int d = threadIdx.x; d < DIH; d += 256) {
        float dp = dpre[(size_t)b * DIH + d];
        float delta = (dp > 20.f) ? dp : log1pf(__expf(dp));
        float xcv = xc[(size_t)b * DIH + d];
        float zv = xz[(size_t)b * 2 * DIH + DIH + d];
        float silz = zv / (1.f + __expf(-zv));
        y[(size_t)b * DIH + d] = (delta * xcv * bc + xcv * Dp[d]) * silz;
    }
}

// ================= host side ======================================================
static inline void gemm(const float* A, int lda, const float* W, const float* bias,
                        float* C, int M, int N, int K, int epi)
{
    dim3 grid((N + 63) / 64, M / 128);
    gemm_mma<<<grid, 256>>>(A, lda, W, bias, C, N, K, epi);
}

static inline float* sym(const void* s)
{
    void* p = nullptr;
    cudaGetSymbolAddress(&p, s);
    return (float*)p;
}

extern "C" void kernel_launch(void* const* d_in, const int* in_sizes, int n_in,
                              void* d_out, int out_size)
{
    const float* image   = (const float*)d_in[0];
    const float* text    = (const float*)d_in[1];
    const float* img_w   = (const float*)d_in[2];
    const float* img_b   = (const float*)d_in[3];
    const float* img_g   = (const float*)d_in[4];
    const float* img_bt  = (const float*)d_in[5];
    const float* txt_w   = (const float*)d_in[6];
    const float* txt_b   = (const float*)d_in[7];
    const float* txt_g   = (const float*)d_in[8];
    const float* txt_bt  = (const float*)d_in[9];
    const float* gate_w1 = (const float*)d_in[10];
    const float* gate_b1 = (const float*)d_in[11];
    const float* gate_w2 = (const float*)d_in[12];
    const float* gate_b2 = (const float*)d_in[13];
    const float* gate_w3 = (const float*)d_in[14];
    const float* gate_b3 = (const float*)d_in[15];
    const float* in_proj = (const float*)d_in[16];
    const float* conv_w  = (const float*)d_in[17];
    const float* conv_b  = (const float*)d_in[18];
    const float* x_proj  = (const float*)d_in[19];
    const float* dt_w    = (const float*)d_in[20];
    const float* dt_b    = (const float*)d_in[21];
    /* d_in[22] = A_log : dead (L=1, h0=0) */
    const float* D_par   = (const float*)d_in[23];
    const float* out_w   = (const float*)d_in[24];
    const float* mn_g    = (const float*)d_in[25];
    const float* mn_b    = (const float*)d_in[26];
    const float* fc_w    = (const float*)d_in[27];
    const float* fc_b    = (const float*)d_in[28];
    const float* fin_g   = (const float*)d_in[29];
    const float* fin_b   = (const float*)d_in[30];

    float* out = (float*)d_out;

    float* f0  = sym(g_f0);  float* f1  = sym(g_f1);
    float* t0  = sym(g_t0);  float* t1  = sym(g_t1);
    float* cat = sym(g_cat); float* h1  = sym(g_h1); float* h2 = sym(g_h2);
    float* x   = sym(g_x);   float* xz  = sym(g_xz); float* xc = sym(g_xc);
    float* dbc = sym(g_dbc); float* dpre = sym(g_dpre);
    float* y   = sym(g_y);   float* mo  = sym(g_mo); float* fc = sym(g_fc);

    const int fused_elems = BATCH * 256;
    float* gate_out = (out_size >= fused_elems + BATCH * 2) ? (out + fused_elems)
                                                            : sym(g_gate_dummy);

    // ---- alignment towers (3x Linear+ReLU+LN each) ----
    const float* a_img = image;
    const float* a_txt = text;
    for (int i = 0; i < 3; i++) {
        gemm(a_img, DIMF, img_w + (size_t)i * DIMF * DIMF, img_b + i * DIMF, f1, BATCH, DIMF, DIMF, 1);
        ln_warp<<<BATCH / 4, 128>>>(f1, nullptr, img_g + i * DIMF, img_bt + i * DIMF, f0, DIMF);
        gemm(a_txt, DIMF, txt_w + (size_t)i * DIMF * DIMF, txt_b + i * DIMF, t1, BATCH, DIMF, DIMF, 1);
        ln_warp<<<BATCH / 4, 128>>>(t1, nullptr, txt_g + i * DIMF, txt_bt + i * DIMF, t0, DIMF);
        a_img = f0; a_txt = t0;
    }

    // ---- gating MLP ----
    concat_kernel<<<(BATCH * DMH + 255) / 256, 256>>>(f0, t0, cat);
    gemm(cat, DMH, gate_w1, gate_b1, h1, BATCH, DIMF, DMH, 1);
    gemm(h1, DIMF, gate_w2, gate_b2, h2, BATCH, 256, DIMF, 1);
    gate_finalize<<<BATCH, 256>>>(h2, gate_w3, gate_b3, f0, t0, gate_out, x);

    // ---- 3 Mamba layers (L=1, SSM collapsed) ----
    for (int i = 0; i < 3; i++) {
        gemm(x, DMH, in_proj + (size_t)i * 2 * DIH * DMH, nullptr, xz, BATCH, 2 * DIH, DMH, 0);
        conv_silu_kernel<<<(BATCH * DIH + 255) / 256, 256>>>(
            xz, conv_w + (size_t)i * DIH * 4, conv_b + (size_t)i * DIH, xc);
        gemm(xc, DIH, x_proj + (size_t)i * 96 * DIH, nullptr, dbc, BATCH, 96, DIH, 0);
        gemm(dbc, 96, dt_w + (size_t)i * DIH * DTRH, dt_b + (size_t)i * DIH, dpre, BATCH, DIH, DTRH, 0);
        y_kernel<<<BATCH, 256>>>(dpre, xc, xz, dbc, D_par + (size_t)i * DIH, y);
        gemm(y, DIH, out_w + (size_t)i * DMH * DIH, nullptr, mo, BATCH, DMH, DIH, 0);
        ln_warp<<<BATCH / 4, 128>>>(mo, x, mn_g + (size_t)i * DMH, mn_b + (size_t)i * DMH, x, DMH);
    }

    // ---- head ----
    gemm(x, DMH, fc_w, fc_b, fc, BATCH, 256, DMH, 0);
    ln_warp<<<BATCH / 4, 128>>>(fc, nullptr, fin_g, fin_b, out, 256);
}

// round 14
// speedup vs baseline: 3.9878x; 1.2898x over previous
#include <cuda_runtime.h>
#include <cuda_bf16.h>
#include <cuda_fp16.h>
#include <cstdint>
#include <math.h>

#define BATCH 1024
#define DIMF  512
#define DMH   1024   // 2*DIM
#define DIH   2048   // 2*DM
#define DTRH  64     // DM/16
#define DSH   16

// ================= scratch (device globals; no allocation allowed) ================
__device__ __align__(256) float g_f0[BATCH*DIMF], g_f1[BATCH*DIMF];
__device__ __align__(256) float g_t0[BATCH*DIMF], g_t1[BATCH*DIMF];
__device__ __align__(256) float g_h1[BATCH*DIMF];
__device__ __align__(256) float g_h2[BATCH*256];
__device__ __align__(256) float g_x[BATCH*DMH];
__device__ __align__(256) float g_z[BATCH*DIH];
__device__ __align__(256) float g_xc[BATCH*DIH];
__device__ __align__(256) float g_dbc[BATCH*96];
__device__ __align__(256) float g_dbcp[4*BATCH*96];
__device__ __align__(256) float g_bc[BATCH];
__device__ __align__(256) float g_y[BATCH*DIH];
__device__ __align__(256) float g_mo[BATCH*DMH];
__device__ __align__(256) float g_fc[BATCH*256];
__device__ __align__(256) float g_cat[BATCH*DMH];
__device__ __align__(256) float g_gate_dummy[BATCH*2];

// ================= HMMA GEMM machinery ============================================
#define SAST 40          // smem row stride in halves

#define MMA_F16(c, a, b) \
    asm volatile("mma.sync.aligned.m16n8k16.row.col.f32.f16.f16.f32 " \
        "{%0,%1,%2,%3}, {%4,%5,%6,%7}, {%8,%9}, {%0,%1,%2,%3};" \
        : "+f"((c)[0]), "+f"((c)[1]), "+f"((c)[2]), "+f"((c)[3]) \
        : "r"((a)[0]), "r"((a)[1]), "r"((a)[2]), "r"((a)[3]), \
          "r"((b)[0]), "r"((b)[1]))

#define LDSM_X4(r0, r1, r2, r3, saddr) \
    asm volatile("ldmatrix.sync.aligned.m8n8.x4.shared.b16 {%0,%1,%2,%3}, [%4];" \
        : "=r"(r0), "=r"(r1), "=r"(r2), "=r"(r3) : "r"(saddr))

__device__ __forceinline__ uint2 f4_to_h4(float4 v) {
    __half2 p0 = __floats2half2_rn(v.x, v.y);
    __half2 p1 = __floats2half2_rn(v.z, v.w);
    uint2 r;
    r.x = *reinterpret_cast<uint32_t*>(&p0);
    r.y = *reinterpret_cast<uint32_t*>(&p1);
    return r;
}

struct Epi {
    const float* cw;   // conv_w  (EPI=2)
    const float* cbv;  // conv_b  (EPI=2)
    float* xc;         // out xc  (EPI=2)
    float* z;          // out z   (EPI=2)
    const float* xcin; // xc      (EPI=3)
    const float* zin;  // z       (EPI=3)
    const float* Dp;   // D_param (EPI=3)
    const float* bc;   // dot(B,C)(EPI=3)
};

__device__ __forceinline__ float sigmoidf_(float v) { return 1.f / (1.f + __expf(-v)); }

// C[M,N] = epi(A[M,K_total] @ W[N,K_total]^T + bias), M = gridDim.y*TM.
// zmode: 0 = plain, 1 = dual-tensor batch over blockIdx.z, 2 = split-K (K = slice size).
// EPI: 0 none, 1 relu, 2 in_proj conv+silu split-write, 3 dt->y fused SSM epilogue.
template<int TM, int EPI>
__global__ void __launch_bounds__(2*TM, (TM==128)?2:4) gemm_k(
    const float* __restrict__ A, const float* __restrict__ A2, int lda,
    const float* __restrict__ W, const float* __restrict__ W2, int ldw,
    const float* __restrict__ bias, const float* __restrict__ bias2,
    float* __restrict__ C, float* __restrict__ C2,
    int N, int K, int zmode, int strideCz, Epi ep)
{
    constexpr int RPI = TM/4;        // rows per gmem-load iteration
    constexpr int BI  = 256/TM;      // B-tile load iterations
    __shared__ __align__(16) __half sA[2][TM * SAST];
    __shared__ __align__(16) __half sB[2][64 * SAST];

    const int tid  = threadIdx.x;
    const int wid  = tid >> 5;
    const int lane = tid & 31;
    const int m0 = blockIdx.y * TM;
    const int n0 = blockIdx.x << 6;

    int kbase = 0;
    if (zmode == 1 && blockIdx.z == 1) { A = A2; W = W2; bias = bias2; C = C2; }
    else if (zmode == 2) { kbase = blockIdx.z * K; C += (size_t)blockIdx.z * strideCz; }

    const int wm = (wid >> 1) << 5;
    const int wn = (wid & 1)  << 5;
    const int g  = lane >> 2;
    const int th = lane & 3;

    const int lr = tid >> 3;            // 0..2*TM/8-1
    const int lc = (tid & 7) << 2;      // 0,4,...,28

    const int a_row  = lane & 15;
    const int a_koff = (lane >> 4) << 3;
    const int b_row  = (lane & 7) + ((lane >> 4) << 3);
    const int b_koff = lane & 8;

    float acc[2][4][4];
#pragma unroll
    for (int mt = 0; mt < 2; mt++)
#pragma unroll
        for (int nt = 0; nt < 4; nt++)
#pragma unroll
            for (int r = 0; r < 4; r++) acc[mt][nt][r] = 0.f;

    const int nchunk = K >> 5;
    float4 aq[4], bq[BI];

    // ---- prologue: chunk 0 ----
#pragma unroll
    for (int i = 0; i < 4; i++)
        aq[i] = *(const float4*)(A + (size_t)(m0 + lr + RPI*i) * lda + kbase + lc);
#pragma unroll
    for (int i = 0; i < BI; i++) {
        int row = lr + RPI*i;
        bq[i] = (n0 + row < N) ? *(const float4*)(W + (size_t)(n0 + row) * ldw + kbase + lc)
                               : make_float4(0.f, 0.f, 0.f, 0.f);
    }
#pragma unroll
    for (int i = 0; i < 4; i++)
        *(uint2*)(&sA[0][(lr + RPI*i) * SAST + lc]) = f4_to_h4(aq[i]);
#pragma unroll
    for (int i = 0; i < BI; i++)
        *(uint2*)(&sB[0][(lr + RPI*i) * SAST + lc]) = f4_to_h4(bq[i]);
    __syncthreads();

    for (int kt = 0; kt < nchunk; kt++) {
        const int cur = kt & 1;
        const bool more = (kt + 1) < nchunk;

        if (more) {
            const int k0 = kbase + ((kt + 1) << 5);
#pragma unroll
            for (int i = 0; i < 4; i++)
                aq[i] = *(const float4*)(A + (size_t)(m0 + lr + RPI*i) * lda + k0 + lc);
#pragma unroll
            for (int i = 0; i < BI; i++) {
                int row = lr + RPI*i;
                bq[i] = (n0 + row < N)
                      ? *(const float4*)(W + (size_t)(n0 + row) * ldw + k0 + lc)
                      : make_float4(0.f, 0.f, 0.f, 0.f);
            }
        }

#pragma unroll
        for (int ks = 0; ks < 2; ks++) {
            const int kb = ks << 4;
            uint32_t af[2][4], bf[4][2];
#pragma unroll
            for (int mt = 0; mt < 2; mt++) {
                uint32_t sa = (uint32_t)__cvta_generic_to_shared(
                    &sA[cur][(wm + mt*16 + a_row) * SAST + kb + a_koff]);
                LDSM_X4(af[mt][0], af[mt][1], af[mt][2], af[mt][3], sa);
            }
#pragma unroll
            for (int ntp = 0; ntp < 2; ntp++) {
                uint32_t sbN = (uint32_t)__cvta_generic_to_shared(
                    &sB[cur][(wn + ntp*16 + b_row) * SAST + kb + b_koff]);
                LDSM_X4(bf[2*ntp][0], bf[2*ntp][1], bf[2*ntp+1][0], bf[2*ntp+1][1], sbN);
            }
#pragma unroll
            for (int mt = 0; mt < 2; mt++)
#pragma unroll
                for (int nt = 0; nt < 4; nt++) MMA_F16(acc[mt][nt], af[mt], bf[nt]);
        }

        if (more) {
            const int nxt = cur ^ 1;
#pragma unroll
            for (int i = 0; i < 4; i++)
                *(uint2*)(&sA[nxt][(lr + RPI*i) * SAST + lc]) = f4_to_h4(aq[i]);
#pragma unroll
            for (int i = 0; i < BI; i++)
                *(uint2*)(&sB[nxt][(lr + RPI*i) * SAST + lc]) = f4_to_h4(bq[i]);
        }
        __syncthreads();
    }

    // ---- epilogue ----
#pragma unroll
    for (int mt = 0; mt < 2; mt++) {
        const int r0 = m0 + wm + mt*16 + g;
        float bc0 = 0.f, bc1 = 0.f;
        if (EPI == 3) { bc0 = ep.bc[r0]; bc1 = ep.bc[r0 + 8]; }
#pragma unroll
        for (int nt = 0; nt < 4; nt++) {
            const int cb = n0 + wn + nt*8 + th*2;
            if (cb >= N) continue;
            float2 v0 = make_float2(acc[mt][nt][0], acc[mt][nt][1]);
            float2 v1 = make_float2(acc[mt][nt][2], acc[mt][nt][3]);
            if (EPI != 2 && bias) {
                float bx = bias[cb], by = bias[cb + 1];
                v0.x += bx; v0.y += by; v1.x += bx; v1.y += by;
            }
            if (EPI == 1) {
                v0.x = fmaxf(v0.x, 0.f); v0.y = fmaxf(v0.y, 0.f);
                v1.x = fmaxf(v1.x, 0.f); v1.y = fmaxf(v1.y, 0.f);
            }
            if (EPI == 2) {
                if (cb < DIH) {
                    float w0 = ep.cw[cb*4 + 3],  w1 = ep.cw[(cb+1)*4 + 3];
                    float c0 = ep.cbv[cb],       c1 = ep.cbv[cb+1];
                    float t;
                    float2 o0, o1;
                    t = v0.x*w0 + c0; o0.x = t * sigmoidf_(t);
                    t = v0.y*w1 + c1; o0.y = t * sigmoidf_(t);
                    t = v1.x*w0 + c0; o1.x = t * sigmoidf_(t);
                    t = v1.y*w1 + c1; o1.y = t * sigmoidf_(t);
                    *(float2*)&ep.xc[(size_t)r0 * DIH + cb]       = o0;
                    *(float2*)&ep.xc[(size_t)(r0+8) * DIH + cb]   = o1;
                } else {
                    int zc = cb - DIH;
                    *(float2*)&ep.z[(size_t)r0 * DIH + zc]        = v0;
                    *(float2*)&ep.z[(size_t)(r0+8) * DIH + zc]    = v1;
                }
            } else if (EPI == 3) {
                float2 x0 = *(const float2*)&ep.xcin[(size_t)r0 * DIH + cb];
                float2 x1 = *(const float2*)&ep.xcin[(size_t)(r0+8) * DIH + cb];
                float2 z0 = *(const float2*)&ep.zin[(size_t)r0 * DIH + cb];
                float2 z1 = *(const float2*)&ep.zin[(size_t)(r0+8) * DIH + cb];
                float2 dd = *(const float2*)&ep.Dp[cb];
                float2 o0, o1;
                {
                    float d0 = (v0.x > 20.f) ? v0.x : log1pf(__expf(v0.x));
                    float d1 = (v0.y > 20.f) ? v0.y : log1pf(__expf(v0.y));
                    o0.x = (d0 * x0.x * bc0 + x0.x * dd.x) * (z0.x * sigmoidf_(z0.x));
                    o0.y = (d1 * x0.y * bc0 + x0.y * dd.y) * (z0.y * sigmoidf_(z0.y));
                    float e0 = (v1.x > 20.f) ? v1.x : log1pf(__expf(v1.x));
                    float e1 = (v1.y > 20.f) ? v1.y : log1pf(__expf(v1.y));
                    o1.x = (e0 * x1.x * bc1 + x1.x * dd.x) * (z1.x * sigmoidf_(z1.x));
                    o1.y = (e1 * x1.y * bc1 + x1.y * dd.y) * (z1.y * sigmoidf_(z1.y));
                }
                *(float2*)&C[(size_t)r0 * N + cb]     = o0;
                *(float2*)&C[(size_t)(r0+8) * N + cb] = o1;
            } else {
                *(float2*)&C[(size_t)r0 * N + cb]     = v0;
                *(float2*)&C[(size_t)(r0+8) * N + cb] = v1;
            }
        }
    }
}

// ================= dbc split-K reduce + bc = dot(B,C) ============================
__global__ __launch_bounds__(96) void reduce_dbc_bc(
    const float* __restrict__ part, float* __restrict__ dbc, float* __restrict__ bc)
{
    const int b = blockIdx.x;
    const int t = threadIdx.x;
    const int idx = b * 96 + t;
    float v = part[idx] + part[BATCH*96 + idx] + part[2*BATCH*96 + idx] + part[3*BATCH*96 + idx];
    dbc[idx] = v;
    __shared__ float sm[32];
    if (t >= 64) sm[t - 64] = v;
    __syncthreads();
    if (t == 0) {
        float s = 0.f;
#pragma unroll
        for (int i = 0; i < 16; i++) s += sm[i] * sm[16 + i];
        bc[b] = s;
    }
}

// ================= LayerNorm: warp per row, register-cached single pass ==========
__device__ __forceinline__ void ln_row(
    const float* __restrict__ x, const float* __restrict__ r,
    const float* __restrict__ g, const float* __restrict__ b,
    float* __restrict__ y, int cols, int lane)
{
    const int n4 = cols >> 2;
    const int nit = n4 >> 5;            // cols/128: 2,4,8
    const float4* x4 = (const float4*)x;
    const float4* r4 = (const float4*)r;
    float4 buf[8];
    float s = 0.f, q = 0.f;
#pragma unroll
    for (int i = 0; i < 8; i++) {
        if (i < nit) {
            float4 v = x4[lane + (i << 5)];
            if (r) { float4 rr = r4[lane + (i << 5)]; v.x += rr.x; v.y += rr.y; v.z += rr.z; v.w += rr.w; }
            buf[i] = v;
            s += v.x + v.y + v.z + v.w;
            q += v.x*v.x + v.y*v.y + v.z*v.z + v.w*v.w;
        }
    }
#pragma unroll
    for (int o = 16; o; o >>= 1) {
        s += __shfl_xor_sync(0xFFFFFFFFu, s, o);
        q += __shfl_xor_sync(0xFFFFFFFFu, q, o);
    }
    const float m = s / cols;
    const float rs = rsqrtf(q / cols - m * m + 1e-5f);
    const float4* g4 = (const float4*)g;
    const float4* b4 = (const float4*)b;
    float4* y4 = (float4*)y;
#pragma unroll
    for (int i = 0; i < 8; i++) {
        if (i < nit) {
            float4 v = buf[i];
            float4 gg = g4[lane + (i << 5)], bb = b4[lane + (i << 5)];
            v.x = (v.x - m) * rs * gg.x + bb.x;
            v.y = (v.y - m) * rs * gg.y + bb.y;
            v.z = (v.z - m) * rs * gg.z + bb.z;
            v.w = (v.w - m) * rs * gg.w + bb.w;
            y4[lane + (i << 5)] = v;
        }
    }
}

__global__ __launch_bounds__(128) void ln_warp(
    const float* __restrict__ X, const float* __restrict__ R,
    const float* __restrict__ g, const float* __restrict__ b,
    float* __restrict__ Y, int cols)
{
    const int row = blockIdx.x * 4 + (threadIdx.x >> 5);
    ln_row(X + (size_t)row * cols, R ? R + (size_t)row * cols : nullptr,
           g, b, Y + (size_t)row * cols, cols, threadIdx.x & 31);
}

// towers: two independent tensors in one launch (blockIdx.y selects)
__global__ __launch_bounds__(128) void ln_warp2(
    const float* __restrict__ X0, const float* __restrict__ X1,
    const float* __restrict__ g0, const float* __restrict__ g1,
    const float* __restrict__ b0, const float* __restrict__ b1,
    float* __restrict__ Y0, float* __restrict__ Y1, int cols)
{
    const int row = blockIdx.x * 4 + (threadIdx.x >> 5);
    const float* X = blockIdx.y ? X1 : X0;
    const float* g = blockIdx.y ? g1 : g0;
    const float* b = blockIdx.y ? b1 : b0;
    float* Y = blockIdx.y ? Y1 : Y0;
    ln_row(X + (size_t)row * cols, nullptr, g, b, Y + (size_t)row * cols, cols, threadIdx.x & 31);
}

// ================= concat img||txt ===============================================
__global__ void concat_kernel(const float* __restrict__ img, const float* __restrict__ txt,
                              float* __restrict__ cat)
{
    int idx = blockIdx.x * blockDim.x + threadIdx.x;
    if (idx >= BATCH * DMH) return;
    int b = idx >> 10, c = idx & 1023;
    cat[idx] = (c < DIMF) ? img[b * DIMF + c] : txt[b * DIMF + c - DIMF];
}

// ================= gate logits + softmax + gated concat ==========================
__global__ __launch_bounds__(256) void gate_finalize(
    const float* __restrict__ h2, const float* __restrict__ w3, const float* __restrict__ b3,
    const float* __restrict__ img, const float* __restrict__ txt,
    float* __restrict__ gate_out, float* __restrict__ x_out)
{
    const int b = blockIdx.x;
    const int tid = threadIdx.x;
    __shared__ float r0[256], r1[256];
    __shared__ float gs[2];
    float h = h2[b * 256 + tid];
    r0[tid] = h * w3[tid];
    r1[tid] = h * w3[256 + tid];
    __syncthreads();
    for (int o = 128; o; o >>= 1) {
        if (tid < o) { r0[tid] += r0[tid + o]; r1[tid] += r1[tid + o]; }
        __syncthreads();
    }
    if (tid == 0) {
        float l0 = r0[0] + b3[0], l1 = r1[0] + b3[1];
        float mx = fmaxf(l0, l1);
        float e0 = expf(l0 - mx), e1 = expf(l1 - mx);
        float inv = 1.f / (e0 + e1);
        gs[0] = e0 * inv; gs[1] = e1 * inv;
        gate_out[b * 2 + 0] = gs[0]; gate_out[b * 2 + 1] = gs[1];
    }
    __syncthreads();
    float g0 = gs[0], g1 = gs[1];
    for (int c = tid; c < DMH; c += 256)
        x_out[b * DMH + c] = (c < DIMF) ? g0 * img[b * DIMF + c] : g1 * txt[b * DIMF + c - DIMF];
}

// ================= host side ======================================================
static inline float* sym(const void* s)
{
    void* p = nullptr;
    cudaGetSymbolAddress(&p, s);
    return (float*)p;
}

extern "C" void kernel_launch(void* const* d_in, const int* in_sizes, int n_in,
                              void* d_out, int out_size)
{
    const float* image   = (const float*)d_in[0];
    const float* text    = (const float*)d_in[1];
    const float* img_w   = (const float*)d_in[2];
    const float* img_b   = (const float*)d_in[3];
    const float* img_g   = (const float*)d_in[4];
    const float* img_bt  = (const float*)d_in[5];
    const float* txt_w   = (const float*)d_in[6];
    const float* txt_b   = (const float*)d_in[7];
    const float* txt_g   = (const float*)d_in[8];
    const float* txt_bt  = (const float*)d_in[9];
    const float* gate_w1 = (const float*)d_in[10];
    const float* gate_b1 = (const float*)d_in[11];
    const float* gate_w2 = (const float*)d_in[12];
    const float* gate_b2 = (const float*)d_in[13];
    const float* gate_w3 = (const float*)d_in[14];
    const float* gate_b3 = (const float*)d_in[15];
    const float* in_proj = (const float*)d_in[16];
    const float* conv_w  = (const float*)d_in[17];
    const float* conv_b  = (const float*)d_in[18];
    const float* x_proj  = (const float*)d_in[19];
    const float* dt_w    = (const float*)d_in[20];
    const float* dt_b    = (const float*)d_in[21];
    /* d_in[22] = A_log : dead (L=1, h0=0) */
    const float* D_par   = (const float*)d_in[23];
    const float* out_w   = (const float*)d_in[24];
    const float* mn_g    = (const float*)d_in[25];
    const float* mn_b    = (const float*)d_in[26];
    const float* fc_w    = (const float*)d_in[27];
    const float* fc_b    = (const float*)d_in[28];
    const float* fin_g   = (const float*)d_in[29];
    const float* fin_b   = (const float*)d_in[30];

    float* out = (float*)d_out;

    float* f0  = sym(g_f0);  float* f1  = sym(g_f1);
    float* t0  = sym(g_t0);  float* t1  = sym(g_t1);
    float* cat = sym(g_cat); float* h1  = sym(g_h1); float* h2 = sym(g_h2);
    float* x   = sym(g_x);   float* z   = sym(g_z);  float* xc = sym(g_xc);
    float* dbc = sym(g_dbc); float* dbcp = sym(g_dbcp); float* bc = sym(g_bc);
    float* y   = sym(g_y);   float* mo  = sym(g_mo); float* fc = sym(g_fc);

    const int fused_elems = BATCH * 256;
    float* gate_out = (out_size >= fused_elems + BATCH * 2) ? (out + fused_elems)
                                                            : sym(g_gate_dummy);

    Epi ep0 = {};

    // ---- alignment towers: batched img/txt GEMM + batched LN ----
    const float* a_img = image;
    const float* a_txt = text;
    for (int i = 0; i < 3; i++) {
        gemm_k<64,1><<<dim3(8,16,2), 128>>>(
            a_img, a_txt, DIMF,
            img_w + (size_t)i*DIMF*DIMF, txt_w + (size_t)i*DIMF*DIMF, DIMF,
            img_b + i*DIMF, txt_b + i*DIMF,
            f1, t1, DIMF, DIMF, 1, 0, ep0);
        ln_warp2<<<dim3(BATCH/4, 2), 128>>>(
            f1, t1, img_g + i*DIMF, txt_g + i*DIMF,
            img_bt + i*DIMF, txt_bt + i*DIMF, f0, t0, DIMF);
        a_img = f0; a_txt = t0;
    }

    // ---- gating MLP ----
    concat_kernel<<<(BATCH*DMH + 255)/256, 256>>>(f0, t0, cat);
    gemm_k<64,1><<<dim3(8,16), 128>>>(cat, nullptr, DMH, gate_w1, nullptr, DMH,
                                      gate_b1, nullptr, h1, nullptr, DIMF, DMH, 0, 0, ep0);
    gemm_k<64,1><<<dim3(4,16), 128>>>(h1, nullptr, DIMF, gate_w2, nullptr, DIMF,
                                      gate_b2, nullptr, h2, nullptr, 256, DIMF, 0, 0, ep0);
    gate_finalize<<<BATCH, 256>>>(h2, gate_w3, gate_b3, f0, t0, gate_out, x);

    // ---- 3 Mamba layers (L=1, SSM collapsed, heavily fused) ----
    for (int i = 0; i < 3; i++) {
        // in_proj + conv(L=1) + silu fused: writes xc (cols<DIH) and z (cols>=DIH)
        Epi epc = {};
        epc.cw  = conv_w + (size_t)i*DIH*4;
        epc.cbv = conv_b + (size_t)i*DIH;
        epc.xc  = xc;  epc.z = z;
        gemm_k<128,2><<<dim3(64,8), 256>>>(
            x, nullptr, DMH, in_proj + (size_t)i*2*DIH*DMH, nullptr, DMH,
            nullptr, nullptr, nullptr, nullptr, 2*DIH, DMH, 0, 0, epc);

        // dbc = xc @ x_proj^T  (N=96), split-K=4 into partials, then reduce + bc
        gemm_k<64,0><<<dim3(2,16,4), 128>>>(
            xc, nullptr, DIH, x_proj + (size_t)i*96*DIH, nullptr, DIH,
            nullptr, nullptr, dbcp, nullptr, 96, DIH/4, 2, BATCH*96, ep0);
        reduce_dbc_bc<<<BATCH, 96>>>(dbcp, dbc, bc);

        // dt GEMM + full collapsed-SSM epilogue -> y
        Epi epy = {};
        epy.xcin = xc; epy.zin = z;
        epy.Dp = D_par + (size_t)i*DIH; epy.bc = bc;
        gemm_k<128,3><<<dim3(32,8), 256>>>(
            dbc, nullptr, 96, dt_w + (size_t)i*DIH*DTRH, nullptr, DTRH,
            dt_b + (size_t)i*DIH, nullptr, y, nullptr, DIH, DTRH, 0, 0, epy);

        // out_proj
        gemm_k<128,0><<<dim3(16,8), 256>>>(
            y, nullptr, DIH, out_w + (size_t)i*DMH*DIH, nullptr, DIH,
            nullptr, nullptr, mo, nullptr, DMH, DIH, 0, 0, ep0);

        // residual + LN
        ln_warp<<<BATCH/4, 128>>>(mo, x, mn_g + (size_t)i*DMH, mn_b + (size_t)i*DMH, x, DMH);
    }

    // ---- head ----
    gemm_k<64,0><<<dim3(4,16), 128>>>(x, nullptr, DMH, fc_w, nullptr, DMH,
                                      fc_b, nullptr, fc, nullptr, 256, DMH, 0, 0, ep0);
    ln_warp<<<BATCH/4, 128>>>(fc, nullptr, fin_g, fin_b, out, 256);
}

// round 15
// speedup vs baseline: 4.5103x; 1.1310x over previous
#include <cuda_runtime.h>
#include <cuda_fp16.h>
#include <cstdint>
#include <math.h>

#define BATCH 1024
#define DIMF  512
#define DMH   1024   // 2*DIM
#define DIH   2048   // 2*DM
#define DTRH  64     // DM/16
#define DSH   16

// ============ fp16 weight/input arena (converted once per launch) =================
// segment offsets (elements)
#define W_IMG   0u
#define W_TXT   786432u
#define W_G1    1572864u
#define W_G2    2097152u
#define W_INP   2228224u
#define W_XPJ   14811136u
#define W_DTW   15400960u
#define W_OUT   15794176u
#define W_FC    22085632u
#define W_IMAGE 22347776u
#define W_TEXT  22872064u
#define W_TOTAL 23396352u

__device__ __align__(256) __half g_wh[W_TOTAL];

// ================= scratch (device globals; no allocation allowed) ================
__device__ __align__(256) float g_f0[BATCH*DIMF], g_f1[BATCH*DIMF];
__device__ __align__(256) float g_t0[BATCH*DIMF], g_t1[BATCH*DIMF];
__device__ __align__(256) __half g_f0h[BATCH*DIMF], g_t0h[BATCH*DIMF];
__device__ __align__(256) __half g_cath[BATCH*DMH];
__device__ __align__(256) __half g_h1h[BATCH*DIMF];
__device__ __align__(256) float g_h2[BATCH*256];
__device__ __align__(256) float g_x[BATCH*DMH];
__device__ __align__(256) __half g_xh[BATCH*DMH];
__device__ __align__(256) float g_z[BATCH*DIH];
__device__ __align__(256) float g_xc[BATCH*DIH];
__device__ __align__(256) __half g_xch[BATCH*DIH];
__device__ __align__(256) float g_dbcp[4*BATCH*96];
__device__ __align__(256) __half g_dbch[BATCH*96];
__device__ __align__(256) float g_bc[BATCH];
__device__ __align__(256) __half g_yh[BATCH*DIH];
__device__ __align__(256) float g_mo[BATCH*DMH];
__device__ __align__(256) float g_fc[BATCH*256];
__device__ __align__(256) float g_gate_dummy[BATCH*2];

// ================= fp32 -> fp16 bulk convert (weights + inputs) ===================
__global__ __launch_bounds__(256) void cvt_all(
    const float* p0, const float* p1, const float* p2, const float* p3,
    const float* p4, const float* p5, const float* p6, const float* p7,
    const float* p8, const float* p9, const float* p10)
{
    const unsigned idx4 = (blockIdx.x * 256u + threadIdx.x) * 4u;
    if (idx4 >= W_TOTAL) return;
    const unsigned offs[12] = {W_IMG, W_TXT, W_G1, W_G2, W_INP, W_XPJ, W_DTW,
                               W_OUT, W_FC, W_IMAGE, W_TEXT, W_TOTAL};
    const float* ptrs[11] = {p0,p1,p2,p3,p4,p5,p6,p7,p8,p9,p10};
    int seg = 0;
#pragma unroll
    for (int i = 1; i < 11; i++) if (idx4 >= offs[i]) seg = i;
    float4 v = *(const float4*)(ptrs[seg] + (idx4 - offs[seg]));
    __half2 lo = __floats2half2_rn(v.x, v.y), hi = __floats2half2_rn(v.z, v.w);
    uint2 u; u.x = *(uint32_t*)&lo; u.y = *(uint32_t*)&hi;
    *(uint2*)(g_wh + idx4) = u;
}

// ================= HMMA GEMM machinery ============================================
#define SAST 40          // smem row stride in halves

#define MMA_F16(c, a, b) \
    asm volatile("mma.sync.aligned.m16n8k16.row.col.f32.f16.f16.f32 " \
        "{%0,%1,%2,%3}, {%4,%5,%6,%7}, {%8,%9}, {%0,%1,%2,%3};" \
        : "+f"((c)[0]), "+f"((c)[1]), "+f"((c)[2]), "+f"((c)[3]) \
        : "r"((a)[0]), "r"((a)[1]), "r"((a)[2]), "r"((a)[3]), \
          "r"((b)[0]), "r"((b)[1]))

#define LDSM_X4(r0, r1, r2, r3, saddr) \
    asm volatile("ldmatrix.sync.aligned.m8n8.x4.shared.b16 {%0,%1,%2,%3}, [%4];" \
        : "=r"(r0), "=r"(r1), "=r"(r2), "=r"(r3) : "r"(saddr))

#define CP_ASYNC16(dst, src) \
    asm volatile("cp.async.cg.shared.global [%0], [%1], 16;" :: "r"(dst), "l"(src))
#define CP_COMMIT() asm volatile("cp.async.commit_group;")
#define CP_WAIT1()  asm volatile("cp.async.wait_group 1;" ::: "memory")
#define CP_WAIT0()  asm volatile("cp.async.wait_group 0;" ::: "memory")

struct Epi {
    const float* cw;    // conv_w  (EPI=2)
    const float* cbv;   // conv_b  (EPI=2)
    float* xc;          // out xc fp32 (EPI=2)
    __half* xch;        // out xc fp16 (EPI=2)
    float* z;           // out z fp32  (EPI=2)
    const float* xcin;  // xc fp32 (EPI=3)
    const float* zin;   // z fp32  (EPI=3)
    const float* Dp;    // D_param (EPI=3)
    const float* bc;    // dot(B,C)(EPI=3)
};

__device__ __forceinline__ float sigmoidf_(float v) { return 1.f / (1.f + __expf(-v)); }

// C[M,N] = epi(A[M,K_total] @ W[N,K_total]^T + bias). A,W fp16 in gmem.
// zmode: 0 plain, 1 dual-tensor over blockIdx.z, 2 split-K (K = slice size).
// EPI: 0 fp32 out, 1 bias+relu fp32 out, 2 in_proj conv+silu split-write,
//      3 dt->y fused SSM (fp16 out via C), 4 bias+relu fp16 out via C.
template<int TM, int EPI>
__global__ void __launch_bounds__(2*TM, (TM==128)?2:4) gemm_h(
    const __half* __restrict__ A, const __half* __restrict__ A2, int lda,
    const __half* __restrict__ W, const __half* __restrict__ W2, int ldw,
    const float* __restrict__ bias, const float* __restrict__ bias2,
    float* __restrict__ C, float* __restrict__ C2,
    int N, int K, int zmode, int strideCz, Epi ep)
{
    constexpr int THREADS = 2*TM;
    constexpr int BPASS = (TM==128) ? 1 : 2;
    __shared__ __align__(16) __half sA[3][TM * SAST];
    __shared__ __align__(16) __half sB[3][64 * SAST];

    const int tid  = threadIdx.x;
    const int wid  = tid >> 5;
    const int lane = tid & 31;
    const int m0 = blockIdx.y * TM;
    const int n0 = blockIdx.x << 6;

    int kbase = 0;
    if (zmode == 1 && blockIdx.z == 1) { A = A2; W = W2; bias = bias2; C = C2; }
    else if (zmode == 2) { kbase = blockIdx.z * K; C += (size_t)blockIdx.z * strideCz; }

    const int wm = (wid >> 1) << 5;
    const int wn = (wid & 1)  << 5;
    const int g  = lane >> 2;
    const int th = lane & 3;

    const int ldr = tid >> 2;           // load row within pass
    const int ldc = (tid & 3) << 3;     // half-offset 0,8,16,24

    const int a_row  = lane & 15;
    const int a_koff = (lane >> 4) << 3;
    const int b_row  = (lane & 7) + ((lane >> 4) << 3);
    const int b_koff = lane & 8;

    float acc[2][4][4];
#pragma unroll
    for (int mt = 0; mt < 2; mt++)
#pragma unroll
        for (int nt = 0; nt < 4; nt++)
#pragma unroll
            for (int r = 0; r < 4; r++) acc[mt][nt][r] = 0.f;

    const int nchunk = K >> 5;

    auto load_stage = [&](int st, int kt) {
        const int k0 = kbase + (kt << 5) + ldc;
#pragma unroll
        for (int p = 0; p < 2; p++) {
            const int row = ldr + p * (TM / 2);
            uint32_t d = (uint32_t)__cvta_generic_to_shared(&sA[st][row * SAST + ldc]);
            const __half* s = A + (size_t)(m0 + row) * lda + k0;
            CP_ASYNC16(d, s);
        }
#pragma unroll
        for (int p = 0; p < BPASS; p++) {
            const int row = ldr + p * (THREADS / 4);
            int wr = n0 + row; if (wr >= N) wr = N - 1;   // clamp: cols >= N discarded
            uint32_t d = (uint32_t)__cvta_generic_to_shared(&sB[st][row * SAST + ldc]);
            const __half* s = W + (size_t)wr * ldw + k0;
            CP_ASYNC16(d, s);
        }
    };

    load_stage(0, 0);
    CP_COMMIT();
    if (nchunk > 1) load_stage(1, 1);
    CP_COMMIT();

    for (int kt = 0; kt < nchunk; kt++) {
        const int st = kt % 3;
        CP_WAIT1();
        __syncthreads();
        if (kt + 2 < nchunk) load_stage((kt + 2) % 3, kt + 2);
        CP_COMMIT();

#pragma unroll
        for (int ks = 0; ks < 2; ks++) {
            const int kb = ks << 4;
            uint32_t af[2][4], bf[4][2];
#pragma unroll
            for (int mt = 0; mt < 2; mt++) {
                uint32_t sa = (uint32_t)__cvta_generic_to_shared(
                    &sA[st][(wm + mt*16 + a_row) * SAST + kb + a_koff]);
                LDSM_X4(af[mt][0], af[mt][1], af[mt][2], af[mt][3], sa);
            }
#pragma unroll
            for (int ntp = 0; ntp < 2; ntp++) {
                uint32_t sbN = (uint32_t)__cvta_generic_to_shared(
                    &sB[st][(wn + ntp*16 + b_row) * SAST + kb + b_koff]);
                LDSM_X4(bf[2*ntp][0], bf[2*ntp][1], bf[2*ntp+1][0], bf[2*ntp+1][1], sbN);
            }
#pragma unroll
            for (int mt = 0; mt < 2; mt++)
#pragma unroll
                for (int nt = 0; nt < 4; nt++) MMA_F16(acc[mt][nt], af[mt], bf[nt]);
        }
    }
    CP_WAIT0();

    // ---- epilogue ----
#pragma unroll
    for (int mt = 0; mt < 2; mt++) {
        const int r0 = m0 + wm + mt*16 + g;
        float bc0 = 0.f, bc1 = 0.f;
        if (EPI == 3) { bc0 = ep.bc[r0]; bc1 = ep.bc[r0 + 8]; }
#pragma unroll
        for (int nt = 0; nt < 4; nt++) {
            const int cb = n0 + wn + nt*8 + th*2;
            if (cb >= N) continue;
            float2 v0 = make_float2(acc[mt][nt][0], acc[mt][nt][1]);
            float2 v1 = make_float2(acc[mt][nt][2], acc[mt][nt][3]);
            if (EPI != 2 && bias) {
                float bx = bias[cb], by = bias[cb + 1];
                v0.x += bx; v0.y += by; v1.x += bx; v1.y += by;
            }
            if (EPI == 1 || EPI == 4) {
                v0.x = fmaxf(v0.x, 0.f); v0.y = fmaxf(v0.y, 0.f);
                v1.x = fmaxf(v1.x, 0.f); v1.y = fmaxf(v1.y, 0.f);
            }
            if (EPI == 2) {
                if (cb < DIH) {
                    float w0 = ep.cw[cb*4 + 3],  w1 = ep.cw[(cb+1)*4 + 3];
                    float c0 = ep.cbv[cb],       c1 = ep.cbv[cb+1];
                    float t;
                    float2 o0, o1;
                    t = v0.x*w0 + c0; o0.x = t * sigmoidf_(t);
                    t = v0.y*w1 + c1; o0.y = t * sigmoidf_(t);
                    t = v1.x*w0 + c0; o1.x = t * sigmoidf_(t);
                    t = v1.y*w1 + c1; o1.y = t * sigmoidf_(t);
                    *(float2*)&ep.xc[(size_t)r0 * DIH + cb]     = o0;
                    *(float2*)&ep.xc[(size_t)(r0+8) * DIH + cb] = o1;
                    *(__half2*)&ep.xch[(size_t)r0 * DIH + cb]     = __floats2half2_rn(o0.x, o0.y);
                    *(__half2*)&ep.xch[(size_t)(r0+8) * DIH + cb] = __floats2half2_rn(o1.x, o1.y);
                } else {
                    int zc = cb - DIH;
                    *(float2*)&ep.z[(size_t)r0 * DIH + zc]     = v0;
                    *(float2*)&ep.z[(size_t)(r0+8) * DIH + zc] = v1;
                }
            } else if (EPI == 3) {
                float2 x0 = *(const float2*)&ep.xcin[(size_t)r0 * DIH + cb];
                float2 x1 = *(const float2*)&ep.xcin[(size_t)(r0+8) * DIH + cb];
                float2 z0 = *(const float2*)&ep.zin[(size_t)r0 * DIH + cb];
                float2 z1 = *(const float2*)&ep.zin[(size_t)(r0+8) * DIH + cb];
                float2 dd = *(const float2*)&ep.Dp[cb];
                float2 o0, o1;
                {
                    float d0 = (v0.x > 20.f) ? v0.x : log1pf(__expf(v0.x));
                    float d1 = (v0.y > 20.f) ? v0.y : log1pf(__expf(v0.y));
                    o0.x = (d0 * x0.x * bc0 + x0.x * dd.x) * (z0.x * sigmoidf_(z0.x));
                    o0.y = (d1 * x0.y * bc0 + x0.y * dd.y) * (z0.y * sigmoidf_(z0.y));
                    float e0 = (v1.x > 20.f) ? v1.x : log1pf(__expf(v1.x));
                    float e1 = (v1.y > 20.f) ? v1.y : log1pf(__expf(v1.y));
                    o1.x = (e0 * x1.x * bc1 + x1.x * dd.x) * (z1.x * sigmoidf_(z1.x));
                    o1.y = (e1 * x1.y * bc1 + x1.y * dd.y) * (z1.y * sigmoidf_(z1.y));
                }
                __half* Ch = (__half*)C;
                *(__half2*)&Ch[(size_t)r0 * N + cb]     = __floats2half2_rn(o0.x, o0.y);
                *(__half2*)&Ch[(size_t)(r0+8) * N + cb] = __floats2half2_rn(o1.x, o1.y);
            } else if (EPI == 4) {
                __half* Ch = (__half*)C;
                *(__half2*)&Ch[(size_t)r0 * N + cb]     = __floats2half2_rn(v0.x, v0.y);
                *(__half2*)&Ch[(size_t)(r0+8) * N + cb] = __floats2half2_rn(v1.x, v1.y);
            } else {
                *(float2*)&C[(size_t)r0 * N + cb]     = v0;
                *(float2*)&C[(size_t)(r0+8) * N + cb] = v1;
            }
        }
    }
}

// ================= dbc split-K reduce + bc = dot(B,C) ============================
__global__ __launch_bounds__(96) void reduce_dbc_bc(
    const float* __restrict__ part, __half* __restrict__ dbch, float* __restrict__ bc)
{
    const int b = blockIdx.x;
    const int t = threadIdx.x;
    const int idx = b * 96 + t;
    float v = part[idx] + part[BATCH*96 + idx] + part[2*BATCH*96 + idx] + part[3*BATCH*96 + idx];
    dbch[idx] = __float2half_rn(v);
    __shared__ float sm[32];
    if (t >= 64) sm[t - 64] = v;
    __syncthreads();
    if (t == 0) {
        float s = 0.f;
#pragma unroll
        for (int i = 0; i < 16; i++) s += sm[i] * sm[16 + i];
        bc[b] = s;
    }
}

// ================= LayerNorm: warp per row, register-cached single pass ==========
__device__ __forceinline__ void ln_row(
    const float* __restrict__ x, const float* __restrict__ r,
    const float* __restrict__ g, const float* __restrict__ b,
    float* __restrict__ y, __half* __restrict__ yh, int cols, int lane)
{
    const int n4 = cols >> 2;
    const int nit = n4 >> 5;            // cols/128: 2,4,8
    const float4* x4 = (const float4*)x;
    const float4* r4 = (const float4*)r;
    float4 buf[8];
    float s = 0.f, q = 0.f;
#pragma unroll
    for (int i = 0; i < 8; i++) {
        if (i < nit) {
            float4 v = x4[lane + (i << 5)];
            if (r) { float4 rr = r4[lane + (i << 5)]; v.x += rr.x; v.y += rr.y; v.z += rr.z; v.w += rr.w; }
            buf[i] = v;
            s += v.x + v.y + v.z + v.w;
            q += v.x*v.x + v.y*v.y + v.z*v.z + v.w*v.w;
        }
    }
#pragma unroll
    for (int o = 16; o; o >>= 1) {
        s += __shfl_xor_sync(0xFFFFFFFFu, s, o);
        q += __shfl_xor_sync(0xFFFFFFFFu, q, o);
    }
    const float m = s / cols;
    const float rs = rsqrtf(q / cols - m * m + 1e-5f);
    const float4* g4 = (const float4*)g;
    const float4* b4 = (const float4*)b;
    float4* y4 = (float4*)y;
#pragma unroll
    for (int i = 0; i < 8; i++) {
        if (i < nit) {
            float4 v = buf[i];
            float4 gg = g4[lane + (i << 5)], bb = b4[lane + (i << 5)];
            v.x = (v.x - m) * rs * gg.x + bb.x;
            v.y = (v.y - m) * rs * gg.y + bb.y;
            v.z = (v.z - m) * rs * gg.z + bb.z;
            v.w = (v.w - m) * rs * gg.w + bb.w;
            y4[lane + (i << 5)] = v;
            if (yh) {
                __half2 lo = __floats2half2_rn(v.x, v.y), hi = __floats2half2_rn(v.z, v.w);
                uint2 u; u.x = *(uint32_t*)&lo; u.y = *(uint32_t*)&hi;
                *(uint2*)(yh + ((size_t)(lane + (i << 5)) << 2)) = u;
            }
        }
    }
}

__global__ __launch_bounds__(128) void ln_warp(
    const float* __restrict__ X, const float* __restrict__ R,
    const float* __restrict__ g, const float* __restrict__ b,
    float* __restrict__ Y, __half* __restrict__ Yh, int cols)
{
    const int row = blockIdx.x * 4 + (threadIdx.x >> 5);
    ln_row(X + (size_t)row * cols, R ? R + (size_t)row * cols : nullptr,
           g, b, Y + (size_t)row * cols, Yh ? Yh + (size_t)row * cols : nullptr,
           cols, threadIdx.x & 31);
}

// towers: two independent tensors in one launch (blockIdx.y selects)
__global__ __launch_bounds__(128) void ln_warp2(
    const float* __restrict__ X0, const float* __restrict__ X1,
    const float* __restrict__ g0, const float* __restrict__ g1,
    const float* __restrict__ b0, const float* __restrict__ b1,
    float* __restrict__ Y0, float* __restrict__ Y1,
    __half* __restrict__ Y0h, __half* __restrict__ Y1h, int cols)
{
    const int row = blockIdx.x * 4 + (threadIdx.x >> 5);
    const float* X = blockIdx.y ? X1 : X0;
    const float* g = blockIdx.y ? g1 : g0;
    const float* b = blockIdx.y ? b1 : b0;
    float* Y  = blockIdx.y ? Y1 : Y0;
    __half* Yh = blockIdx.y ? Y1h : Y0h;
    ln_row(X + (size_t)row * cols, nullptr, g, b,
           Y + (size_t)row * cols, Yh + (size_t)row * cols, cols, threadIdx.x & 31);
}

// ================= concat img||txt -> fp16 =======================================
__global__ void concat_kernel(const float* __restrict__ img, const float* __restrict__ txt,
                              __half* __restrict__ cath)
{
    int idx = blockIdx.x * blockDim.x + threadIdx.x;
    if (idx >= BATCH * DMH) return;
    int b = idx >> 10, c = idx & 1023;
    float v = (c < DIMF) ? img[b * DIMF + c] : txt[b * DIMF + c - DIMF];
    cath[idx] = __float2half_rn(v);
}

// ================= gate logits + softmax + gated concat ==========================
__global__ __launch_bounds__(256) void gate_finalize(
    const float* __restrict__ h2, const float* __restrict__ w3, const float* __restrict__ b3,
    const float* __restrict__ img, const float* __restrict__ txt,
    float* __restrict__ gate_out, float* __restrict__ x_out, __half* __restrict__ xh_out)
{
    const int b = blockIdx.x;
    const int tid = threadIdx.x;
    __shared__ float r0[256], r1[256];
    __shared__ float gs[2];
    float h = h2[b * 256 + tid];
    r0[tid] = h * w3[tid];
    r1[tid] = h * w3[256 + tid];
    __syncthreads();
    for (int o = 128; o; o >>= 1) {
        if (tid < o) { r0[tid] += r0[tid + o]; r1[tid] += r1[tid + o]; }
        __syncthreads();
    }
    if (tid == 0) {
        float l0 = r0[0] + b3[0], l1 = r1[0] + b3[1];
        float mx = fmaxf(l0, l1);
        float e0 = expf(l0 - mx), e1 = expf(l1 - mx);
        float inv = 1.f / (e0 + e1);
        gs[0] = e0 * inv; gs[1] = e1 * inv;
        gate_out[b * 2 + 0] = gs[0]; gate_out[b * 2 + 1] = gs[1];
    }
    __syncthreads();
    float g0 = gs[0], g1 = gs[1];
    for (int c = tid; c < DMH; c += 256) {
        float v = (c < DIMF) ? g0 * img[b * DIMF + c] : g1 * txt[b * DIMF + c - DIMF];
        x_out[b * DMH + c] = v;
        xh_out[b * DMH + c] = __float2half_rn(v);
    }
}

// ================= host side ======================================================
static inline void* symv(const void* s)
{
    void* p = nullptr;
    cudaGetSymbolAddress(&p, s);
    return p;
}

extern "C" void kernel_launch(void* const* d_in, const int* in_sizes, int n_in,
                              void* d_out, int out_size)
{
    const float* image   = (const float*)d_in[0];
    const float* text    = (const float*)d_in[1];
    const float* img_w   = (const float*)d_in[2];
    const float* img_b   = (const float*)d_in[3];
    const float* img_g   = (const float*)d_in[4];
    const float* img_bt  = (const float*)d_in[5];
    const float* txt_w   = (const float*)d_in[6];
    const float* txt_b   = (const float*)d_in[7];
    const float* txt_g   = (const float*)d_in[8];
    const float* txt_bt  = (const float*)d_in[9];
    const float* gate_w1 = (const float*)d_in[10];
    const float* gate_b1 = (const float*)d_in[11];
    const float* gate_w2 = (const float*)d_in[12];
    const float* gate_b2 = (const float*)d_in[13];
    const float* gate_w3 = (const float*)d_in[14];
    const float* gate_b3 = (const float*)d_in[15];
    const float* in_proj = (const float*)d_in[16];
    const float* conv_w  = (const float*)d_in[17];
    const float* conv_b  = (const float*)d_in[18];
    const float* x_proj  = (const float*)d_in[19];
    const float* dt_w    = (const float*)d_in[20];
    const float* dt_b    = (const float*)d_in[21];
    /* d_in[22] = A_log : dead (L=1, h0=0) */
    const float* D_par   = (const float*)d_in[23];
    const float* out_w   = (const float*)d_in[24];
    const float* mn_g    = (const float*)d_in[25];
    const float* mn_b    = (const float*)d_in[26];
    const float* fc_w    = (const float*)d_in[27];
    const float* fc_b    = (const float*)d_in[28];
    const float* fin_g   = (const float*)d_in[29];
    const float* fin_b   = (const float*)d_in[30];

    float* out = (float*)d_out;

    float*  f0   = (float*)symv(g_f0);   float*  f1   = (float*)symv(g_f1);
    float*  t0   = (float*)symv(g_t0);   float*  t1   = (float*)symv(g_t1);
    __half* f0h  = (__half*)symv(g_f0h); __half* t0h  = (__half*)symv(g_t0h);
    __half* cath = (__half*)symv(g_cath);
    __half* h1h  = (__half*)symv(g_h1h); float*  h2   = (float*)symv(g_h2);
    float*  x    = (float*)symv(g_x);    __half* xh   = (__half*)symv(g_xh);
    float*  z    = (float*)symv(g_z);
    float*  xc   = (float*)symv(g_xc);   __half* xch  = (__half*)symv(g_xch);
    float*  dbcp = (float*)symv(g_dbcp); __half* dbch = (__half*)symv(g_dbch);
    float*  bc   = (float*)symv(g_bc);   __half* yh   = (__half*)symv(g_yh);
    float*  mo   = (float*)symv(g_mo);   float*  fc   = (float*)symv(g_fc);
    __half* wh   = (__half*)symv(g_wh);

    const int fused_elems = BATCH * 256;
    float* gate_out = (out_size >= fused_elems + BATCH * 2) ? (out + fused_elems)
                                                            : (float*)symv(g_gate_dummy);

    Epi ep0 = {};

    // ---- convert all weights + inputs to fp16 (identical numerics to in-GEMM cvt) ----
    cvt_all<<<(W_TOTAL/4 + 255)/256, 256>>>(
        img_w, txt_w, gate_w1, gate_w2, in_proj, x_proj, dt_w, out_w, fc_w,
        image, text);

    // ---- alignment towers: batched img/txt GEMM + batched LN ----
    const __half* a_img = wh + W_IMAGE;
    const __half* a_txt = wh + W_TEXT;
    for (int i = 0; i < 3; i++) {
        gemm_h<64,1><<<dim3(8,16,2), 128>>>(
            a_img, a_txt, DIMF,
            wh + W_IMG + (size_t)i*DIMF*DIMF, wh + W_TXT + (size_t)i*DIMF*DIMF, DIMF,
            img_b + i*DIMF, txt_b + i*DIMF,
            f1, t1, DIMF, DIMF, 1, 0, ep0);
        ln_warp2<<<dim3(BATCH/4, 2), 128>>>(
            f1, t1, img_g + i*DIMF, txt_g + i*DIMF,
            img_bt + i*DIMF, txt_bt + i*DIMF, f0, t0, f0h, t0h, DIMF);
        a_img = f0h; a_txt = t0h;
    }

    // ---- gating MLP ----
    concat_kernel<<<(BATCH*DMH + 255)/256, 256>>>(f0, t0, cath);
    gemm_h<64,4><<<dim3(8,16), 128>>>(cath, nullptr, DMH, wh + W_G1, nullptr, DMH,
                                      gate_b1, nullptr, (float*)h1h, nullptr, DIMF, DMH, 0, 0, ep0);
    gemm_h<64,1><<<dim3(4,16), 128>>>(h1h, nullptr, DIMF, wh + W_G2, nullptr, DIMF,
                                      gate_b2, nullptr, h2, nullptr, 256, DIMF, 0, 0, ep0);
    gate_finalize<<<BATCH, 256>>>(h2, gate_w3, gate_b3, f0, t0, gate_out, x, xh);

    // ---- 3 Mamba layers (L=1, SSM collapsed, heavily fused) ----
    for (int i = 0; i < 3; i++) {
        // in_proj + conv(L=1) + silu fused: writes xc fp32+fp16 (cols<DIH), z fp32
        Epi epc = {};
        epc.cw  = conv_w + (size_t)i*DIH*4;
        epc.cbv = conv_b + (size_t)i*DIH;
        epc.xc  = xc;  epc.xch = xch;  epc.z = z;
        gemm_h<128,2><<<dim3(64,8), 256>>>(
            xh, nullptr, DMH, wh + W_INP + (size_t)i*2*DIH*DMH, nullptr, DMH,
            nullptr, nullptr, nullptr, nullptr, 2*DIH, DMH, 0, 0, epc);

        // dbc = xc @ x_proj^T  (N=96), split-K=4 into partials, then reduce + bc
        gemm_h<64,0><<<dim3(2,16,4), 128>>>(
            xch, nullptr, DIH, wh + W_XPJ + (size_t)i*96*DIH, nullptr, DIH,
            nullptr, nullptr, dbcp, nullptr, 96, DIH/4, 2, BATCH*96, ep0);
        reduce_dbc_bc<<<BATCH, 96>>>(dbcp, dbch, bc);

        // dt GEMM + full collapsed-SSM epilogue -> y (fp16)
        Epi epy = {};
        epy.xcin = xc; epy.zin = z;
        epy.Dp = D_par + (size_t)i*DIH; epy.bc = bc;
        gemm_h<128,3><<<dim3(32,8), 256>>>(
            dbch, nullptr, 96, wh + W_DTW + (size_t)i*DIH*DTRH, nullptr, DTRH,
            dt_b + (size_t)i*DIH, nullptr, (float*)yh, nullptr, DIH, DTRH, 0, 0, epy);

        // out_proj
        gemm_h<128,0><<<dim3(16,8), 256>>>(
            yh, nullptr, DIH, wh + W_OUT + (size_t)i*DMH*DIH, nullptr, DIH,
            nullptr, nullptr, mo, nullptr, DMH, DIH, 0, 0, ep0);

        // residual + LN (fp32 + fp16 copies)
        ln_warp<<<BATCH/4, 128>>>(mo, x, mn_g + (size_t)i*DMH, mn_b + (size_t)i*DMH, x, xh, DMH);
    }

    // ---- head ----
    gemm_h<64,0><<<dim3(4,16), 128>>>(xh, nullptr, DMH, wh + W_FC, nullptr, DMH,
                                      fc_b, nullptr, fc, nullptr, 256, DMH, 0, 0, ep0);
    ln_warp<<<BATCH/4, 128>>>(fc, nullptr, fin_g, fin_b, out, nullptr, 256);
}

// round 16
// speedup vs baseline: 4.5383x; 1.0062x over previous
#include <cuda_runtime.h>
#include <cuda_fp16.h>
#include <cstdint>
#include <math.h>

#define BATCH 1024
#define DIMF  512
#define DMH   1024   // 2*DIM
#define DIH   2048   // 2*DM
#define DTRH  64     // DM/16
#define DSH   16

// ============ fp16 weight/input arena (converted once per launch) =================
#define W_IMG   0u
#define W_TXT   786432u
#define W_G1    1572864u
#define W_G2    2097152u
#define W_INP   2228224u
#define W_XPJ   14811136u
#define W_DTW   15400960u
#define W_OUT   15794176u
#define W_FC    22085632u
#define W_IMAGE 22347776u
#define W_TEXT  22872064u
#define W_TOTAL 23396352u

__device__ __align__(256) __half g_wh[W_TOTAL];

// ================= scratch (device globals; no allocation allowed) ================
__device__ __align__(256) float g_f0[BATCH*DIMF], g_f1[BATCH*DIMF];
__device__ __align__(256) float g_t0[BATCH*DIMF], g_t1[BATCH*DIMF];
__device__ __align__(256) __half g_f0h[BATCH*DIMF], g_t0h[BATCH*DIMF];
__device__ __align__(256) __half g_h1h[BATCH*DIMF];
__device__ __align__(256) float g_h2[BATCH*256];
__device__ __align__(256) float g_x[BATCH*DMH];
__device__ __align__(256) __half g_xh[BATCH*DMH];
__device__ __align__(256) float g_z[BATCH*DIH];
__device__ __align__(256) float g_xc[BATCH*DIH];
__device__ __align__(256) __half g_xch[BATCH*DIH];
__device__ __align__(256) float g_dbcp[4*BATCH*96];
__device__ __align__(256) __half g_dbch[BATCH*96];
__device__ __align__(256) float g_bc[BATCH];
__device__ __align__(256) __half g_yh[BATCH*DIH];
__device__ __align__(256) float g_mo[BATCH*DMH];
__device__ __align__(256) float g_fc[BATCH*256];
__device__ __align__(256) float g_gate_dummy[BATCH*2];

// ================= fp32 -> fp16 bulk convert (weights + inputs) ===================
__global__ __launch_bounds__(256) void cvt_all(
    const float* p0, const float* p1, const float* p2, const float* p3,
    const float* p4, const float* p5, const float* p6, const float* p7,
    const float* p8, const float* p9, const float* p10)
{
    const unsigned idx4 = (blockIdx.x * 256u + threadIdx.x) * 4u;
    if (idx4 >= W_TOTAL) return;
    const unsigned offs[12] = {W_IMG, W_TXT, W_G1, W_G2, W_INP, W_XPJ, W_DTW,
                               W_OUT, W_FC, W_IMAGE, W_TEXT, W_TOTAL};
    const float* ptrs[11] = {p0,p1,p2,p3,p4,p5,p6,p7,p8,p9,p10};
    int seg = 0;
#pragma unroll
    for (int i = 1; i < 11; i++) if (idx4 >= offs[i]) seg = i;
    float4 v = *(const float4*)(ptrs[seg] + (idx4 - offs[seg]));
    __half2 lo = __floats2half2_rn(v.x, v.y), hi = __floats2half2_rn(v.z, v.w);
    uint2 u; u.x = *(uint32_t*)&lo; u.y = *(uint32_t*)&hi;
    *(uint2*)(g_wh + idx4) = u;
}

// ================= HMMA GEMM machinery ============================================
#define SAST 40          // smem row stride in halves

#define MMA_F16(c, a, b) \
    asm volatile("mma.sync.aligned.m16n8k16.row.col.f32.f16.f16.f32 " \
        "{%0,%1,%2,%3}, {%4,%5,%6,%7}, {%8,%9}, {%0,%1,%2,%3};" \
        : "+f"((c)[0]), "+f"((c)[1]), "+f"((c)[2]), "+f"((c)[3]) \
        : "r"((a)[0]), "r"((a)[1]), "r"((a)[2]), "r"((a)[3]), \
          "r"((b)[0]), "r"((b)[1]))

#define LDSM_X4(r0, r1, r2, r3, saddr) \
    asm volatile("ldmatrix.sync.aligned.m8n8.x4.shared.b16 {%0,%1,%2,%3}, [%4];" \
        : "=r"(r0), "=r"(r1), "=r"(r2), "=r"(r3) : "r"(saddr))

#define CP_ASYNC16(dst, src) \
    asm volatile("cp.async.cg.shared.global [%0], [%1], 16;" :: "r"(dst), "l"(src))
#define CP_COMMIT() asm volatile("cp.async.commit_group;")
#define CP_WAIT1()  asm volatile("cp.async.wait_group 1;" ::: "memory")
#define CP_WAIT0()  asm volatile("cp.async.wait_group 0;" ::: "memory")

struct Epi {
    const float* cw;    // conv_w  (EPI=2)
    const float* cbv;   // conv_b  (EPI=2)
    float* xc;          // out xc fp32 (EPI=2)
    __half* xch;        // out xc fp16 (EPI=2)
    float* z;           // out z fp32  (EPI=2)
    const float* xcin;  // xc fp32 (EPI=3)
    const float* zin;   // z fp32  (EPI=3)
    const float* Dp;    // D_param (EPI=3)
    const float* bc;    // dot(B,C)(EPI=3)
};

__device__ __forceinline__ float sigmoidf_(float v) { return 1.f / (1.f + __expf(-v)); }

// ---- shared epilogue element handler (per (r0,cb) pair of fp32x2 values) ----
template<int EPI>
__device__ __forceinline__ void epi_store(
    int r0, int cb, int N, float2 v0, float2 v1,
    const float* bias, float* C, const Epi& ep, float bc0, float bc1)
{
    if (EPI != 2 && bias) {
        float bx = bias[cb], by = bias[cb + 1];
        v0.x += bx; v0.y += by; v1.x += bx; v1.y += by;
    }
    if (EPI == 1 || EPI == 4) {
        v0.x = fmaxf(v0.x, 0.f); v0.y = fmaxf(v0.y, 0.f);
        v1.x = fmaxf(v1.x, 0.f); v1.y = fmaxf(v1.y, 0.f);
    }
    if (EPI == 2) {
        if (cb < DIH) {
            float w0 = ep.cw[cb*4 + 3],  w1 = ep.cw[(cb+1)*4 + 3];
            float c0 = ep.cbv[cb],       c1 = ep.cbv[cb+1];
            float t;
            float2 o0, o1;
            t = v0.x*w0 + c0; o0.x = t * sigmoidf_(t);
            t = v0.y*w1 + c1; o0.y = t * sigmoidf_(t);
            t = v1.x*w0 + c0; o1.x = t * sigmoidf_(t);
            t = v1.y*w1 + c1; o1.y = t * sigmoidf_(t);
            *(float2*)&ep.xc[(size_t)r0 * DIH + cb]     = o0;
            *(float2*)&ep.xc[(size_t)(r0+8) * DIH + cb] = o1;
            *(__half2*)&ep.xch[(size_t)r0 * DIH + cb]     = __floats2half2_rn(o0.x, o0.y);
            *(__half2*)&ep.xch[(size_t)(r0+8) * DIH + cb] = __floats2half2_rn(o1.x, o1.y);
        } else {
            int zc = cb - DIH;
            *(float2*)&ep.z[(size_t)r0 * DIH + zc]     = v0;
            *(float2*)&ep.z[(size_t)(r0+8) * DIH + zc] = v1;
        }
    } else if (EPI == 3) {
        float2 x0 = *(const float2*)&ep.xcin[(size_t)r0 * DIH + cb];
        float2 x1 = *(const float2*)&ep.xcin[(size_t)(r0+8) * DIH + cb];
        float2 z0 = *(const float2*)&ep.zin[(size_t)r0 * DIH + cb];
        float2 z1 = *(const float2*)&ep.zin[(size_t)(r0+8) * DIH + cb];
        float2 dd = *(const float2*)&ep.Dp[cb];
        float2 o0, o1;
        float d0 = (v0.x > 20.f) ? v0.x : log1pf(__expf(v0.x));
        float d1 = (v0.y > 20.f) ? v0.y : log1pf(__expf(v0.y));
        o0.x = (d0 * x0.x * bc0 + x0.x * dd.x) * (z0.x * sigmoidf_(z0.x));
        o0.y = (d1 * x0.y * bc0 + x0.y * dd.y) * (z0.y * sigmoidf_(z0.y));
        float e0 = (v1.x > 20.f) ? v1.x : log1pf(__expf(v1.x));
        float e1 = (v1.y > 20.f) ? v1.y : log1pf(__expf(v1.y));
        o1.x = (e0 * x1.x * bc1 + x1.x * dd.x) * (z1.x * sigmoidf_(z1.x));
        o1.y = (e1 * x1.y * bc1 + x1.y * dd.y) * (z1.y * sigmoidf_(z1.y));
        __half* Ch = (__half*)C;
        *(__half2*)&Ch[(size_t)r0 * N + cb]     = __floats2half2_rn(o0.x, o0.y);
        *(__half2*)&Ch[(size_t)(r0+8) * N + cb] = __floats2half2_rn(o1.x, o1.y);
    } else if (EPI == 4) {
        __half* Ch = (__half*)C;
        *(__half2*)&Ch[(size_t)r0 * N + cb]     = __floats2half2_rn(v0.x, v0.y);
        *(__half2*)&Ch[(size_t)(r0+8) * N + cb] = __floats2half2_rn(v1.x, v1.y);
    } else {
        *(float2*)&C[(size_t)r0 * N + cb]     = v0;
        *(float2*)&C[(size_t)(r0+8) * N + cb] = v1;
    }
}

// C[M,N] = epi(A[M,K_total] @ W[N,K_total]^T + bias). A,W fp16 in gmem.
// zmode: 0 plain, 1 dual-tensor over blockIdx.z, 2 split-K (K = slice size),
//        3 concat: A supplies k<lda, A2 supplies k>=lda (both row stride lda).
template<int TM, int EPI>
__global__ void __launch_bounds__(2*TM, (TM==128)?2:4) gemm_h(
    const __half* __restrict__ A, const __half* __restrict__ A2, int lda,
    const __half* __restrict__ W, const __half* __restrict__ W2, int ldw,
    const float* __restrict__ bias, const float* __restrict__ bias2,
    float* __restrict__ C, float* __restrict__ C2,
    int N, int K, int zmode, int strideCz, Epi ep)
{
    constexpr int THREADS = 2*TM;
    constexpr int BPASS = (TM==128) ? 1 : 2;
    __shared__ __align__(16) __half sA[3][TM * SAST];
    __shared__ __align__(16) __half sB[3][64 * SAST];

    const int tid  = threadIdx.x;
    const int wid  = tid >> 5;
    const int lane = tid & 31;
    const int m0 = blockIdx.y * TM;
    const int n0 = blockIdx.x << 6;

    int kbase = 0;
    if (zmode == 1 && blockIdx.z == 1) { A = A2; W = W2; bias = bias2; C = C2; }
    else if (zmode == 2) { kbase = blockIdx.z * K; C += (size_t)blockIdx.z * strideCz; }

    const int wm = (wid >> 1) << 5;
    const int wn = (wid & 1)  << 5;
    const int g  = lane >> 2;
    const int th = lane & 3;

    const int ldr = tid >> 2;
    const int ldc = (tid & 3) << 3;

    const int a_row  = lane & 15;
    const int a_koff = (lane >> 4) << 3;
    const int b_row  = (lane & 7) + ((lane >> 4) << 3);
    const int b_koff = lane & 8;

    float acc[2][4][4];
#pragma unroll
    for (int mt = 0; mt < 2; mt++)
#pragma unroll
        for (int nt = 0; nt < 4; nt++)
#pragma unroll
            for (int r = 0; r < 4; r++) acc[mt][nt][r] = 0.f;

    const int nchunk = K >> 5;

    auto load_stage = [&](int st, int kt) {
        const int k0 = kbase + (kt << 5) + ldc;
        const __half* Asrc = A; int ka = k0;
        if (zmode == 3 && k0 >= lda) { Asrc = A2; ka = k0 - lda; }
#pragma unroll
        for (int p = 0; p < 2; p++) {
            const int row = ldr + p * (TM / 2);
            uint32_t d = (uint32_t)__cvta_generic_to_shared(&sA[st][row * SAST + ldc]);
            CP_ASYNC16(d, Asrc + (size_t)(m0 + row) * lda + ka);
        }
#pragma unroll
        for (int p = 0; p < BPASS; p++) {
            const int row = ldr + p * (THREADS / 4);
            int wr = n0 + row; if (wr >= N) wr = N - 1;   // clamp: cols >= N discarded
            uint32_t d = (uint32_t)__cvta_generic_to_shared(&sB[st][row * SAST + ldc]);
            CP_ASYNC16(d, W + (size_t)wr * ldw + k0);
        }
    };

    load_stage(0, 0);
    CP_COMMIT();
    if (nchunk > 1) load_stage(1, 1);
    CP_COMMIT();

    for (int kt = 0; kt < nchunk; kt++) {
        const int st = kt % 3;
        CP_WAIT1();
        __syncthreads();
        if (kt + 2 < nchunk) load_stage((kt + 2) % 3, kt + 2);
        CP_COMMIT();

#pragma unroll
        for (int ks = 0; ks < 2; ks++) {
            const int kb = ks << 4;
            uint32_t af[2][4], bf[4][2];
#pragma unroll
            for (int mt = 0; mt < 2; mt++) {
                uint32_t sa = (uint32_t)__cvta_generic_to_shared(
                    &sA[st][(wm + mt*16 + a_row) * SAST + kb + a_koff]);
                LDSM_X4(af[mt][0], af[mt][1], af[mt][2], af[mt][3], sa);
            }
#pragma unroll
            for (int ntp = 0; ntp < 2; ntp++) {
                uint32_t sbN = (uint32_t)__cvta_generic_to_shared(
                    &sB[st][(wn + ntp*16 + b_row) * SAST + kb + b_koff]);
                LDSM_X4(bf[2*ntp][0], bf[2*ntp][1], bf[2*ntp+1][0], bf[2*ntp+1][1], sbN);
            }
#pragma unroll
            for (int mt = 0; mt < 2; mt++)
#pragma unroll
                for (int nt = 0; nt < 4; nt++) MMA_F16(acc[mt][nt], af[mt], bf[nt]);
        }
    }
    CP_WAIT0();

#pragma unroll
    for (int mt = 0; mt < 2; mt++) {
        const int r0 = m0 + wm + mt*16 + g;
        float bc0 = 0.f, bc1 = 0.f;
        if (EPI == 3) { bc0 = ep.bc[r0]; bc1 = ep.bc[r0 + 8]; }
#pragma unroll
        for (int nt = 0; nt < 4; nt++) {
            const int cb = n0 + wn + nt*8 + th*2;
            if (cb >= N) continue;
            float2 v0 = make_float2(acc[mt][nt][0], acc[mt][nt][1]);
            float2 v1 = make_float2(acc[mt][nt][2], acc[mt][nt][3]);
            epi_store<EPI>(r0, cb, N, v0, v1, bias, C, ep, bc0, bc1);
        }
    }
}

// ================= big-tile GEMM: 128x128x32, warp tile 64x32 =====================
// Same K-chunk order as gemm_h -> bit-identical accumulation per output element.
#define BIG_SMEM (3 * 128 * SAST * 2 * 2)   // 61440 bytes

template<int EPI>
__global__ void __launch_bounds__(256, 2) gemm_big(
    const __half* __restrict__ A, int lda,
    const __half* __restrict__ W, int ldw,
    const float* __restrict__ bias,
    float* __restrict__ C, int N, int K, Epi ep)
{
    extern __shared__ __align__(16) __half dyn[];
    __half* sAb = dyn;                       // [3][128*SAST]
    __half* sBb = dyn + 3 * 128 * SAST;      // [3][128*SAST]

    const int tid  = threadIdx.x;
    const int wid  = tid >> 5;
    const int lane = tid & 31;
    const int m0 = blockIdx.y << 7;
    const int n0 = blockIdx.x << 7;

    const int wm = (wid >> 2) << 6;     // 0,64
    const int wn = (wid & 3)  << 5;     // 0,32,64,96
    const int g  = lane >> 2;
    const int th = lane & 3;

    const int ldr = tid >> 2;           // 0..63
    const int ldc = (tid & 3) << 3;

    const int a_row  = lane & 15;
    const int a_koff = (lane >> 4) << 3;
    const int b_row  = (lane & 7) + ((lane >> 4) << 3);
    const int b_koff = lane & 8;

    float acc[4][4][4];
#pragma unroll
    for (int mt = 0; mt < 4; mt++)
#pragma unroll
        for (int nt = 0; nt < 4; nt++)
#pragma unroll
            for (int r = 0; r < 4; r++) acc[mt][nt][r] = 0.f;

    const int nchunk = K >> 5;

    auto load_stage = [&](int st, int kt) {
        const int k0 = (kt << 5) + ldc;
        __half* bA = sAb + st * 128 * SAST;
        __half* bB = sBb + st * 128 * SAST;
#pragma unroll
        for (int p = 0; p < 2; p++) {
            const int row = ldr + (p << 6);
            uint32_t d = (uint32_t)__cvta_generic_to_shared(&bA[row * SAST + ldc]);
            CP_ASYNC16(d, A + (size_t)(m0 + row) * lda + k0);
        }
#pragma unroll
        for (int p = 0; p < 2; p++) {
            const int row = ldr + (p << 6);
            int wr = n0 + row; if (wr >= N) wr = N - 1;
            uint32_t d = (uint32_t)__cvta_generic_to_shared(&bB[row * SAST + ldc]);
            CP_ASYNC16(d, W + (size_t)wr * ldw + k0);
        }
    };

    load_stage(0, 0);
    CP_COMMIT();
    if (nchunk > 1) load_stage(1, 1);
    CP_COMMIT();

    for (int kt = 0; kt < nchunk; kt++) {
        const int st = kt % 3;
        const __half* cA = sAb + st * 128 * SAST;
        const __half* cB = sBb + st * 128 * SAST;
        CP_WAIT1();
        __syncthreads();
        if (kt + 2 < nchunk) load_stage((kt + 2) % 3, kt + 2);
        CP_COMMIT();

#pragma unroll
        for (int ks = 0; ks < 2; ks++) {
            const int kb = ks << 4;
            uint32_t af[4][4], bf[4][2];
#pragma unroll
            for (int mt = 0; mt < 4; mt++) {
                uint32_t sa = (uint32_t)__cvta_generic_to_shared(
                    &cA[(wm + mt*16 + a_row) * SAST + kb + a_koff]);
                LDSM_X4(af[mt][0], af[mt][1], af[mt][2], af[mt][3], sa);
            }
#pragma unroll
            for (int ntp = 0; ntp < 2; ntp++) {
                uint32_t sbN = (uint32_t)__cvta_generic_to_shared(
                    &cB[(wn + ntp*16 + b_row) * SAST + kb + b_koff]);
                LDSM_X4(bf[2*ntp][0], bf[2*ntp][1], bf[2*ntp+1][0], bf[2*ntp+1][1], sbN);
            }
#pragma unroll
            for (int mt = 0; mt < 4; mt++)
#pragma unroll
                for (int nt = 0; nt < 4; nt++) MMA_F16(acc[mt][nt], af[mt], bf[nt]);
        }
    }
    CP_WAIT0();

#pragma unroll
    for (int mt = 0; mt < 4; mt++) {
        const int r0 = m0 + wm + mt*16 + g;
        float bc0 = 0.f, bc1 = 0.f;
        if (EPI == 3) { bc0 = ep.bc[r0]; bc1 = ep.bc[r0 + 8]; }
#pragma unroll
        for (int nt = 0; nt < 4; nt++) {
            const int cb = n0 + wn + nt*8 + th*2;
            if (cb >= N) continue;
            float2 v0 = make_float2(acc[mt][nt][0], acc[mt][nt][1]);
            float2 v1 = make_float2(acc[mt][nt][2], acc[mt][nt][3]);
            epi_store<EPI>(r0, cb, N, v0, v1, bias, C, ep, bc0, bc1);
        }
    }
}

// ================= dbc split-K reduce + bc = dot(B,C) ============================
__global__ __launch_bounds__(96) void reduce_dbc_bc(
    const float* __restrict__ part, __half* __restrict__ dbch, float* __restrict__ bc)
{
    const int b = blockIdx.x;
    const int t = threadIdx.x;
    const int idx = b * 96 + t;
    float v = part[idx] + part[BATCH*96 + idx] + part[2*BATCH*96 + idx] + part[3*BATCH*96 + idx];
    dbch[idx] = __float2half_rn(v);
    __shared__ float sm[32];
    if (t >= 64) sm[t - 64] = v;
    __syncthreads();
    if (t == 0) {
        float s = 0.f;
#pragma unroll
        for (int i = 0; i < 16; i++) s += sm[i] * sm[16 + i];
        bc[b] = s;
    }
}

// ================= LayerNorm: warp per row, register-cached single pass ==========
__device__ __forceinline__ void ln_row(
    const float* __restrict__ x, const float* __restrict__ r,
    const float* __restrict__ g, const float* __restrict__ b,
    float* __restrict__ y, __half* __restrict__ yh, int cols, int lane)
{
    const int n4 = cols >> 2;
    const int nit = n4 >> 5;
    const float4* x4 = (const float4*)x;
    const float4* r4 = (const float4*)r;
    float4 buf[8];
    float s = 0.f, q = 0.f;
#pragma unroll
    for (int i = 0; i < 8; i++) {
        if (i < nit) {
            float4 v = x4[lane + (i << 5)];
            if (r) { float4 rr = r4[lane + (i << 5)]; v.x += rr.x; v.y += rr.y; v.z += rr.z; v.w += rr.w; }
            buf[i] = v;
            s += v.x + v.y + v.z + v.w;
            q += v.x*v.x + v.y*v.y + v.z*v.z + v.w*v.w;
        }
    }
#pragma unroll
    for (int o = 16; o; o >>= 1) {
        s += __shfl_xor_sync(0xFFFFFFFFu, s, o);
        q += __shfl_xor_sync(0xFFFFFFFFu, q, o);
    }
    const float m = s / cols;
    const float rs = rsqrtf(q / cols - m * m + 1e-5f);
    const float4* g4 = (const float4*)g;
    const float4* b4 = (const float4*)b;
    float4* y4 = (float4*)y;
#pragma unroll
    for (int i = 0; i < 8; i++) {
        if (i < nit) {
            float4 v = buf[i];
            float4 gg = g4[lane + (i << 5)], bb = b4[lane + (i << 5)];
            v.x = (v.x - m) * rs * gg.x + bb.x;
            v.y = (v.y - m) * rs * gg.y + bb.y;
            v.z = (v.z - m) * rs * gg.z + bb.z;
            v.w = (v.w - m) * rs * gg.w + bb.w;
            y4[lane + (i << 5)] = v;
            if (yh) {
                __half2 lo = __floats2half2_rn(v.x, v.y), hi = __floats2half2_rn(v.z, v.w);
                uint2 u; u.x = *(uint32_t*)&lo; u.y = *(uint32_t*)&hi;
                *(uint2*)(yh + ((size_t)(lane + (i << 5)) << 2)) = u;
            }
        }
    }
}

__global__ __launch_bounds__(128) void ln_warp(
    const float* __restrict__ X, const float* __restrict__ R,
    const float* __restrict__ g, const float* __restrict__ b,
    float* __restrict__ Y, __half* __restrict__ Yh, int cols)
{
    const int row = blockIdx.x * 4 + (threadIdx.x >> 5);
    ln_row(X + (size_t)row * cols, R ? R + (size_t)row * cols : nullptr,
           g, b, Y + (size_t)row * cols, Yh ? Yh + (size_t)row * cols : nullptr,
           cols, threadIdx.x & 31);
}

__global__ __launch_bounds__(128) void ln_warp2(
    const float* __restrict__ X0, const float* __restrict__ X1,
    const float* __restrict__ g0, const float* __restrict__ g1,
    const float* __restrict__ b0, const float* __restrict__ b1,
    float* __restrict__ Y0, float* __restrict__ Y1,
    __half* __restrict__ Y0h, __half* __restrict__ Y1h, int cols)
{
    const int row = blockIdx.x * 4 + (threadIdx.x >> 5);
    const float* X = blockIdx.y ? X1 : X0;
    const float* g = blockIdx.y ? g1 : g0;
    const float* b = blockIdx.y ? b1 : b0;
    float* Y  = blockIdx.y ? Y1 : Y0;
    __half* Yh = blockIdx.y ? Y1h : Y0h;
    ln_row(X + (size_t)row * cols, nullptr, g, b,
           Y + (size_t)row * cols, Yh + (size_t)row * cols, cols, threadIdx.x & 31);
}

// ================= gate logits + softmax + gated concat ==========================
__global__ __launch_bounds__(256) void gate_finalize(
    const float* __restrict__ h2, const float* __restrict__ w3, const float* __restrict__ b3,
    const float* __restrict__ img, const float* __restrict__ txt,
    float* __restrict__ gate_out, float* __restrict__ x_out, __half* __restrict__ xh_out)
{
    const int b = blockIdx.x;
    const int tid = threadIdx.x;
    __shared__ float r0[256], r1[256];
    __shared__ float gs[2];
    float h = h2[b * 256 + tid];
    r0[tid] = h * w3[tid];
    r1[tid] = h * w3[256 + tid];
    __syncthreads();
    for (int o = 128; o; o >>= 1) {
        if (tid < o) { r0[tid] += r0[tid + o]; r1[tid] += r1[tid + o]; }
        __syncthreads();
    }
    if (tid == 0) {
        float l0 = r0[0] + b3[0], l1 = r1[0] + b3[1];
        float mx = fmaxf(l0, l1);
        float e0 = expf(l0 - mx), e1 = expf(l1 - mx);
        float inv = 1.f / (e0 + e1);
        gs[0] = e0 * inv; gs[1] = e1 * inv;
        gate_out[b * 2 + 0] = gs[0]; gate_out[b * 2 + 1] = gs[1];
    }
    __syncthreads();
    float g0 = gs[0], g1 = gs[1];
    for (int c = tid; c < DMH; c += 256) {
        float v = (c < DIMF) ? g0 * img[b * DIMF + c] : g1 * txt[b * DIMF + c - DIMF];
        x_out[b * DMH + c] = v;
        xh_out[b * DMH + c] = __float2half_rn(v);
    }
}

// ================= host side ======================================================
static inline void* symv(const void* s)
{
    void* p = nullptr;
    cudaGetSymbolAddress(&p, s);
    return p;
}

extern "C" void kernel_launch(void* const* d_in, const int* in_sizes, int n_in,
                              void* d_out, int out_size)
{
    cudaFuncSetAttribute(gemm_big<2>, cudaFuncAttributeMaxDynamicSharedMemorySize, BIG_SMEM);

    const float* image   = (const float*)d_in[0];
    const float* text    = (const float*)d_in[1];
    const float* img_w   = (const float*)d_in[2];
    const float* img_b   = (const float*)d_in[3];
    const float* img_g   = (const float*)d_in[4];
    const float* img_bt  = (const float*)d_in[5];
    const float* txt_w   = (const float*)d_in[6];
    const float* txt_b   = (const float*)d_in[7];
    const float* txt_g   = (const float*)d_in[8];
    const float* txt_bt  = (const float*)d_in[9];
    const float* gate_w1 = (const float*)d_in[10];
    const float* gate_b1 = (const float*)d_in[11];
    const float* gate_w2 = (const float*)d_in[12];
    const float* gate_b2 = (const float*)d_in[13];
    const float* gate_w3 = (const float*)d_in[14];
    const float* gate_b3 = (const float*)d_in[15];
    const float* in_proj = (const float*)d_in[16];
    const float* conv_w  = (const float*)d_in[17];
    const float* conv_b  = (const float*)d_in[18];
    const float* x_proj  = (const float*)d_in[19];
    const float* dt_w    = (const float*)d_in[20];
    const float* dt_b    = (const float*)d_in[21];
    /* d_in[22] = A_log : dead (L=1, h0=0) */
    const float* D_par   = (const float*)d_in[23];
    const float* out_w   = (const float*)d_in[24];
    const float* mn_g    = (const float*)d_in[25];
    const float* mn_b    = (const float*)d_in[26];
    const float* fc_w    = (const float*)d_in[27];
    const float* fc_b    = (const float*)d_in[28];
    const float* fin_g   = (const float*)d_in[29];
    const float* fin_b   = (const float*)d_in[30];

    float* out = (float*)d_out;

    float*  f0   = (float*)symv(g_f0);   float*  f1   = (float*)symv(g_f1);
    float*  t0   = (float*)symv(g_t0);   float*  t1   = (float*)symv(g_t1);
    __half* f0h  = (__half*)symv(g_f0h); __half* t0h  = (__half*)symv(g_t0h);
    __half* h1h  = (__half*)symv(g_h1h); float*  h2   = (float*)symv(g_h2);
    float*  x    = (float*)symv(g_x);    __half* xh   = (__half*)symv(g_xh);
    float*  z    = (float*)symv(g_z);
    float*  xc   = (float*)symv(g_xc);   __half* xch  = (__half*)symv(g_xch);
    float*  dbcp = (float*)symv(g_dbcp); __half* dbch = (__half*)symv(g_dbch);
    float*  bc   = (float*)symv(g_bc);   __half* yh   = (__half*)symv(g_yh);
    float*  mo   = (float*)symv(g_mo);   float*  fc   = (float*)symv(g_fc);
    __half* wh   = (__half*)symv(g_wh);

    const int fused_elems = BATCH * 256;
    float* gate_out = (out_size >= fused_elems + BATCH * 2) ? (out + fused_elems)
                                                            : (float*)symv(g_gate_dummy);

    Epi ep0 = {};

    // ---- convert all weights + inputs to fp16 (identical numerics to in-GEMM cvt) ----
    cvt_all<<<(W_TOTAL/4 + 255)/256, 256>>>(
        img_w, txt_w, gate_w1, gate_w2, in_proj, x_proj, dt_w, out_w, fc_w,
        image, text);

    // ---- alignment towers: batched img/txt GEMM + batched LN ----
    const __half* a_img = wh + W_IMAGE;
    const __half* a_txt = wh + W_TEXT;
    for (int i = 0; i < 3; i++) {
        gemm_h<64,1><<<dim3(8,16,2), 128>>>(
            a_img, a_txt, DIMF,
            wh + W_IMG + (size_t)i*DIMF*DIMF, wh + W_TXT + (size_t)i*DIMF*DIMF, DIMF,
            img_b + i*DIMF, txt_b + i*DIMF,
            f1, t1, DIMF, DIMF, 1, 0, ep0);
        ln_warp2<<<dim3(BATCH/4, 2), 128>>>(
            f1, t1, img_g + i*DIMF, txt_g + i*DIMF,
            img_bt + i*DIMF, txt_bt + i*DIMF, f0, t0, f0h, t0h, DIMF);
        a_img = f0h; a_txt = t0h;
    }

    // ---- gating MLP (concat folded into W1 GEMM via zmode=3) ----
    gemm_h<64,4><<<dim3(8,16), 128>>>(f0h, t0h, DIMF, wh + W_G1, nullptr, DMH,
                                      gate_b1, nullptr, (float*)h1h, nullptr, DIMF, DMH, 3, 0, ep0);
    gemm_h<64,1><<<dim3(4,16), 128>>>(h1h, nullptr, DIMF, wh + W_G2, nullptr, DIMF,
                                      gate_b2, nullptr, h2, nullptr, 256, DIMF, 0, 0, ep0);
    gate_finalize<<<BATCH, 256>>>(h2, gate_w3, gate_b3, f0, t0, gate_out, x, xh);

    // ---- 3 Mamba layers (L=1, SSM collapsed, heavily fused) ----
    for (int i = 0; i < 3; i++) {
        // in_proj + conv(L=1) + silu fused: big 128x128 tile
        Epi epc = {};
        epc.cw  = conv_w + (size_t)i*DIH*4;
        epc.cbv = conv_b + (size_t)i*DIH;
        epc.xc  = xc;  epc.xch = xch;  epc.z = z;
        gemm_big<2><<<dim3(32,8), 256, BIG_SMEM>>>(
            xh, DMH, wh + W_INP + (size_t)i*2*DIH*DMH, DMH,
            nullptr, nullptr, 2*DIH, DMH, epc);

        // dbc = xc @ x_proj^T  (N=96), split-K=4 into partials, then reduce + bc
        gemm_h<64,0><<<dim3(2,16,4), 128>>>(
            xch, nullptr, DIH, wh + W_XPJ + (size_t)i*96*DIH, nullptr, DIH,
            nullptr, nullptr, dbcp, nullptr, 96, DIH/4, 2, BATCH*96, ep0);
        reduce_dbc_bc<<<BATCH, 96>>>(dbcp, dbch, bc);

        // dt GEMM + full collapsed-SSM epilogue -> y (fp16)
        Epi epy = {};
        epy.xcin = xc; epy.zin = z;
        epy.Dp = D_par + (size_t)i*DIH; epy.bc = bc;
        gemm_h<128,3><<<dim3(32,8), 256>>>(
            dbch, nullptr, 96, wh + W_DTW + (size_t)i*DIH*DTRH, nullptr, DTRH,
            dt_b + (size_t)i*DIH, nullptr, (float*)yh, nullptr, DIH, DTRH, 0, 0, epy);

        // out_proj
        gemm_h<128,0><<<dim3(16,8), 256>>>(
            yh, nullptr, DIH, wh + W_OUT + (size_t)i*DMH*DIH, nullptr, DIH,
            nullptr, nullptr, mo, nullptr, DMH, DIH, 0, 0, ep0);

        // residual + LN (fp32 + fp16 copies)
        ln_warp<<<BATCH/4, 128>>>(mo, x, mn_g + (size_t)i*DMH, mn_b + (size_t)i*DMH, x, xh, DMH);
    }

    // ---- head ----
    gemm_h<64,0><<<dim3(4,16), 128>>>(xh, nullptr, DMH, wh + W_FC, nullptr, DMH,
                                      fc_b, nullptr, fc, nullptr, 256, DMH, 0, 0, ep0);
    ln_warp<<<BATCH/4, 128>>>(fc, nullptr, fin_g, fin_b, out, nullptr, 256);
}

// round 17
// speedup vs baseline: 4.9283x; 1.0859x over previous
#include <cuda_runtime.h>
#include <cuda_fp16.h>
#include <cstdint>
#include <math.h>

#define BATCH 1024
#define DIMF  512
#define DMH   1024   // 2*DIM
#define DIH   2048   // 2*DM
#define DTRH  64     // DM/16
#define DSH   16

// ============ fp16 weight/input arena (converted once per launch) =================
#define W_IMG   0u
#define W_TXT   786432u
#define W_G1    1572864u
#define W_G2    2097152u
#define W_INP   2228224u
#define W_XPJ   14811136u
#define W_DTW   15400960u
#define W_OUT   15794176u
#define W_FC    22085632u
#define W_IMAGE 22347776u
#define W_TEXT  22872064u
#define W_TOTAL 23396352u

__device__ __align__(256) __half g_wh[W_TOTAL];

// ================= scratch (device globals; no allocation allowed) ================
__device__ __align__(256) float g_f0[BATCH*DIMF], g_f1[BATCH*DIMF];
__device__ __align__(256) float g_t0[BATCH*DIMF], g_t1[BATCH*DIMF];
__device__ __align__(256) __half g_f0h[BATCH*DIMF], g_t0h[BATCH*DIMF];
__device__ __align__(256) __half g_h1h[BATCH*DIMF];
__device__ __align__(256) float g_h2[BATCH*256];
__device__ __align__(256) float g_x[BATCH*DMH];
__device__ __align__(256) __half g_xh[BATCH*DMH];
__device__ __align__(256) float g_z[BATCH*DIH];
__device__ __align__(256) float g_xc[BATCH*DIH];
__device__ __align__(256) __half g_xch[BATCH*DIH];
__device__ __align__(256) float g_dbcp[4*BATCH*96];
__device__ __align__(256) __half g_dbch[BATCH*96];
__device__ __align__(256) float g_bc[BATCH];
__device__ __align__(256) __half g_yh[BATCH*DIH];
__device__ __align__(256) float g_mo[BATCH*DMH];
__device__ __align__(256) float g_fc[BATCH*256];
__device__ __align__(256) float g_gate_dummy[BATCH*2];

// ================= fp32 -> fp16 bulk convert (weights + inputs) ===================
__global__ __launch_bounds__(256) void cvt_all(
    const float* p0, const float* p1, const float* p2, const float* p3,
    const float* p4, const float* p5, const float* p6, const float* p7,
    const float* p8, const float* p9, const float* p10)
{
    const unsigned idx4 = (blockIdx.x * 256u + threadIdx.x) * 4u;
    if (idx4 >= W_TOTAL) return;
    const unsigned offs[12] = {W_IMG, W_TXT, W_G1, W_G2, W_INP, W_XPJ, W_DTW,
                               W_OUT, W_FC, W_IMAGE, W_TEXT, W_TOTAL};
    const float* ptrs[11] = {p0,p1,p2,p3,p4,p5,p6,p7,p8,p9,p10};
    int seg = 0;
#pragma unroll
    for (int i = 1; i < 11; i++) if (idx4 >= offs[i]) seg = i;
    float4 v = *(const float4*)(ptrs[seg] + (idx4 - offs[seg]));
    __half2 lo = __floats2half2_rn(v.x, v.y), hi = __floats2half2_rn(v.z, v.w);
    uint2 u; u.x = *(uint32_t*)&lo; u.y = *(uint32_t*)&hi;
    *(uint2*)(g_wh + idx4) = u;
}

// ================= HMMA GEMM machinery ============================================
#define SAST 40          // smem row stride in halves

#define MMA_F16(c, a, b) \
    asm volatile("mma.sync.aligned.m16n8k16.row.col.f32.f16.f16.f32 " \
        "{%0,%1,%2,%3}, {%4,%5,%6,%7}, {%8,%9}, {%0,%1,%2,%3};" \
        : "+f"((c)[0]), "+f"((c)[1]), "+f"((c)[2]), "+f"((c)[3]) \
        : "r"((a)[0]), "r"((a)[1]), "r"((a)[2]), "r"((a)[3]), \
          "r"((b)[0]), "r"((b)[1]))

#define LDSM_X4(r0, r1, r2, r3, saddr) \
    asm volatile("ldmatrix.sync.aligned.m8n8.x4.shared.b16 {%0,%1,%2,%3}, [%4];" \
        : "=r"(r0), "=r"(r1), "=r"(r2), "=r"(r3) : "r"(saddr))

#define CP_ASYNC16(dst, src) \
    asm volatile("cp.async.cg.shared.global [%0], [%1], 16;" :: "r"(dst), "l"(src))
#define CP_COMMIT() asm volatile("cp.async.commit_group;")
#define CP_WAIT0()  asm volatile("cp.async.wait_group 0;" ::: "memory")

struct Epi {
    const float* cw;    // conv_w  (EPI=2)
    const float* cbv;   // conv_b  (EPI=2)
    float* xc;          // out xc fp32 (EPI=2)
    __half* xch;        // out xc fp16 (EPI=2)
    float* z;           // out z fp32  (EPI=2)
    const float* xcin;  // xc fp32 (EPI=3)
    const float* zin;   // z fp32  (EPI=3)
    const float* Dp;    // D_param (EPI=3)
    const float* bc;    // dot(B,C)(EPI=3)
};

__device__ __forceinline__ float sigmoidf_(float v) { return 1.f / (1.f + __expf(-v)); }

// ---- shared epilogue element handler (per (r0,cb) pair of fp32x2 values) ----
template<int EPI>
__device__ __forceinline__ void epi_store(
    int r0, int cb, int N, float2 v0, float2 v1,
    const float* bias, float* C, const Epi& ep, float bc0, float bc1)
{
    if (EPI != 2 && bias) {
        float bx = bias[cb], by = bias[cb + 1];
        v0.x += bx; v0.y += by; v1.x += bx; v1.y += by;
    }
    if (EPI == 1 || EPI == 4) {
        v0.x = fmaxf(v0.x, 0.f); v0.y = fmaxf(v0.y, 0.f);
        v1.x = fmaxf(v1.x, 0.f); v1.y = fmaxf(v1.y, 0.f);
    }
    if (EPI == 2) {
        if (cb < DIH) {
            float w0 = ep.cw[cb*4 + 3],  w1 = ep.cw[(cb+1)*4 + 3];
            float c0 = ep.cbv[cb],       c1 = ep.cbv[cb+1];
            float t;
            float2 o0, o1;
            t = v0.x*w0 + c0; o0.x = t * sigmoidf_(t);
            t = v0.y*w1 + c1; o0.y = t * sigmoidf_(t);
            t = v1.x*w0 + c0; o1.x = t * sigmoidf_(t);
            t = v1.y*w1 + c1; o1.y = t * sigmoidf_(t);
            *(float2*)&ep.xc[(size_t)r0 * DIH + cb]     = o0;
            *(float2*)&ep.xc[(size_t)(r0+8) * DIH + cb] = o1;
            *(__half2*)&ep.xch[(size_t)r0 * DIH + cb]     = __floats2half2_rn(o0.x, o0.y);
            *(__half2*)&ep.xch[(size_t)(r0+8) * DIH + cb] = __floats2half2_rn(o1.x, o1.y);
        } else {
            int zc = cb - DIH;
            *(float2*)&ep.z[(size_t)r0 * DIH + zc]     = v0;
            *(float2*)&ep.z[(size_t)(r0+8) * DIH + zc] = v1;
        }
    } else if (EPI == 3) {
        float2 x0 = *(const float2*)&ep.xcin[(size_t)r0 * DIH + cb];
        float2 x1 = *(const float2*)&ep.xcin[(size_t)(r0+8) * DIH + cb];
        float2 z0 = *(const float2*)&ep.zin[(size_t)r0 * DIH + cb];
        float2 z1 = *(const float2*)&ep.zin[(size_t)(r0+8) * DIH + cb];
        float2 dd = *(const float2*)&ep.Dp[cb];
        float2 o0, o1;
        float d0 = (v0.x > 20.f) ? v0.x : log1pf(__expf(v0.x));
        float d1 = (v0.y > 20.f) ? v0.y : log1pf(__expf(v0.y));
        o0.x = (d0 * x0.x * bc0 + x0.x * dd.x) * (z0.x * sigmoidf_(z0.x));
        o0.y = (d1 * x0.y * bc0 + x0.y * dd.y) * (z0.y * sigmoidf_(z0.y));
        float e0 = (v1.x > 20.f) ? v1.x : log1pf(__expf(v1.x));
        float e1 = (v1.y > 20.f) ? v1.y : log1pf(__expf(v1.y));
        o1.x = (e0 * x1.x * bc1 + x1.x * dd.x) * (z1.x * sigmoidf_(z1.x));
        o1.y = (e1 * x1.y * bc1 + x1.y * dd.y) * (z1.y * sigmoidf_(z1.y));
        __half* Ch = (__half*)C;
        *(__half2*)&Ch[(size_t)r0 * N + cb]     = __floats2half2_rn(o0.x, o0.y);
        *(__half2*)&Ch[(size_t)(r0+8) * N + cb] = __floats2half2_rn(o1.x, o1.y);
    } else if (EPI == 4) {
        __half* Ch = (__half*)C;
        *(__half2*)&Ch[(size_t)r0 * N + cb]     = __floats2half2_rn(v0.x, v0.y);
        *(__half2*)&Ch[(size_t)(r0+8) * N + cb] = __floats2half2_rn(v1.x, v1.y);
    } else {
        *(float2*)&C[(size_t)r0 * N + cb]     = v0;
        *(float2*)&C[(size_t)(r0+8) * N + cb] = v1;
    }
}

// C[M,N] = epi(A[M,K_total] @ W[N,K_total]^T + bias). A,W fp16 in gmem.
// zmode: 0 plain, 1 dual-tensor over blockIdx.z, 2 split-K (K = slice size),
//        3 concat: A supplies k<lda, A2 supplies k>=lda (both row stride lda).
template<int TM, int EPI>
__global__ void __launch_bounds__(2*TM, (TM==128)?2:4) gemm_h(
    const __half* __restrict__ A, const __half* __restrict__ A2, int lda,
    const __half* __restrict__ W, const __half* __restrict__ W2, int ldw,
    const float* __restrict__ bias, const float* __restrict__ bias2,
    float* __restrict__ C, float* __restrict__ C2,
    int N, int K, int zmode, int strideCz, Epi ep)
{
    constexpr int THREADS = 2*TM;
    constexpr int BPASS = (TM==128) ? 1 : 2;
    constexpr int NST = (TM==128) ? 3 : 4;   // 4-stage for TM=64 (41KB static)
    __shared__ __align__(16) __half sA[NST][TM * SAST];
    __shared__ __align__(16) __half sB[NST][64 * SAST];

    const int tid  = threadIdx.x;
    const int wid  = tid >> 5;
    const int lane = tid & 31;
    const int m0 = blockIdx.y * TM;
    const int n0 = blockIdx.x << 6;

    int kbase = 0;
    if (zmode == 1 && blockIdx.z == 1) { A = A2; W = W2; bias = bias2; C = C2; }
    else if (zmode == 2) { kbase = blockIdx.z * K; C += (size_t)blockIdx.z * strideCz; }

    const int wm = (wid >> 1) << 5;
    const int wn = (wid & 1)  << 5;
    const int g  = lane >> 2;
    const int th = lane & 3;

    const int ldr = tid >> 2;
    const int ldc = (tid & 3) << 3;

    const int a_row  = lane & 15;
    const int a_koff = (lane >> 4) << 3;
    const int b_row  = (lane & 7) + ((lane >> 4) << 3);
    const int b_koff = lane & 8;

    float acc[2][4][4];
#pragma unroll
    for (int mt = 0; mt < 2; mt++)
#pragma unroll
        for (int nt = 0; nt < 4; nt++)
#pragma unroll
            for (int r = 0; r < 4; r++) acc[mt][nt][r] = 0.f;

    const int nchunk = K >> 5;

    auto load_stage = [&](int st, int kt) {
        const int k0 = kbase + (kt << 5) + ldc;
        const __half* Asrc = A; int ka = k0;
        if (zmode == 3 && k0 >= lda) { Asrc = A2; ka = k0 - lda; }
#pragma unroll
        for (int p = 0; p < 2; p++) {
            const int row = ldr + p * (TM / 2);
            uint32_t d = (uint32_t)__cvta_generic_to_shared(&sA[st][row * SAST + ldc]);
            CP_ASYNC16(d, Asrc + (size_t)(m0 + row) * lda + ka);
        }
#pragma unroll
        for (int p = 0; p < BPASS; p++) {
            const int row = ldr + p * (THREADS / 4);
            int wr = n0 + row; if (wr >= N) wr = N - 1;   // clamp: cols >= N discarded
            uint32_t d = (uint32_t)__cvta_generic_to_shared(&sB[st][row * SAST + ldc]);
            CP_ASYNC16(d, W + (size_t)wr * ldw + k0);
        }
    };

#pragma unroll
    for (int s = 0; s < NST-1; s++) {
        if (s < nchunk) load_stage(s, s);
        CP_COMMIT();
    }

    for (int kt = 0; kt < nchunk; kt++) {
        const int st = kt % NST;
        asm volatile("cp.async.wait_group %0;" :: "n"(NST-2) : "memory");
        __syncthreads();
        if (kt + NST-1 < nchunk) load_stage((kt + NST-1) % NST, kt + NST-1);
        CP_COMMIT();

#pragma unroll
        for (int ks = 0; ks < 2; ks++) {
            const int kb = ks << 4;
            uint32_t af[2][4], bf[4][2];
#pragma unroll
            for (int mt = 0; mt < 2; mt++) {
                uint32_t sa = (uint32_t)__cvta_generic_to_shared(
                    &sA[st][(wm + mt*16 + a_row) * SAST + kb + a_koff]);
                LDSM_X4(af[mt][0], af[mt][1], af[mt][2], af[mt][3], sa);
            }
#pragma unroll
            for (int ntp = 0; ntp < 2; ntp++) {
                uint32_t sbN = (uint32_t)__cvta_generic_to_shared(
                    &sB[st][(wn + ntp*16 + b_row) * SAST + kb + b_koff]);
                LDSM_X4(bf[2*ntp][0], bf[2*ntp][1], bf[2*ntp+1][0], bf[2*ntp+1][1], sbN);
            }
#pragma unroll
            for (int mt = 0; mt < 2; mt++)
#pragma unroll
                for (int nt = 0; nt < 4; nt++) MMA_F16(acc[mt][nt], af[mt], bf[nt]);
        }
    }
    CP_WAIT0();

#pragma unroll
    for (int mt = 0; mt < 2; mt++) {
        const int r0 = m0 + wm + mt*16 + g;
        float bc0 = 0.f, bc1 = 0.f;
        if (EPI == 3) { bc0 = ep.bc[r0]; bc1 = ep.bc[r0 + 8]; }
#pragma unroll
        for (int nt = 0; nt < 4; nt++) {
            const int cb = n0 + wn + nt*8 + th*2;
            if (cb >= N) continue;
            float2 v0 = make_float2(acc[mt][nt][0], acc[mt][nt][1]);
            float2 v1 = make_float2(acc[mt][nt][2], acc[mt][nt][3]);
            epi_store<EPI>(r0, cb, N, v0, v1, bias, C, ep, bc0, bc1);
        }
    }
}

// ================= big-tile GEMM: 128x128x32, warp tile 64x32, 4-stage ============
#define BIG_NST 4
#define BIG_SMEM (BIG_NST * 128 * SAST * 2 * 2)   // 81920 bytes

template<int EPI>
__global__ void __launch_bounds__(256, 2) gemm_big(
    const __half* __restrict__ A, int lda,
    const __half* __restrict__ W, int ldw,
    const float* __restrict__ bias,
    float* __restrict__ C, int N, int K, Epi ep)
{
    extern __shared__ __align__(16) __half dyn[];
    __half* sAb = dyn;                              // [NST][128*SAST]
    __half* sBb = dyn + BIG_NST * 128 * SAST;       // [NST][128*SAST]

    const int tid  = threadIdx.x;
    const int wid  = tid >> 5;
    const int lane = tid & 31;
    const int m0 = blockIdx.y << 7;
    const int n0 = blockIdx.x << 7;

    const int wm = (wid >> 2) << 6;
    const int wn = (wid & 3)  << 5;
    const int g  = lane >> 2;
    const int th = lane & 3;

    const int ldr = tid >> 2;
    const int ldc = (tid & 3) << 3;

    const int a_row  = lane & 15;
    const int a_koff = (lane >> 4) << 3;
    const int b_row  = (lane & 7) + ((lane >> 4) << 3);
    const int b_koff = lane & 8;

    float acc[4][4][4];
#pragma unroll
    for (int mt = 0; mt < 4; mt++)
#pragma unroll
        for (int nt = 0; nt < 4; nt++)
#pragma unroll
            for (int r = 0; r < 4; r++) acc[mt][nt][r] = 0.f;

    const int nchunk = K >> 5;

    auto load_stage = [&](int st, int kt) {
        const int k0 = (kt << 5) + ldc;
        __half* bA = sAb + st * 128 * SAST;
        __half* bB = sBb + st * 128 * SAST;
#pragma unroll
        for (int p = 0; p < 2; p++) {
            const int row = ldr + (p << 6);
            uint32_t d = (uint32_t)__cvta_generic_to_shared(&bA[row * SAST + ldc]);
            CP_ASYNC16(d, A + (size_t)(m0 + row) * lda + k0);
        }
#pragma unroll
        for (int p = 0; p < 2; p++) {
            const int row = ldr + (p << 6);
            int wr = n0 + row; if (wr >= N) wr = N - 1;
            uint32_t d = (uint32_t)__cvta_generic_to_shared(&bB[row * SAST + ldc]);
            CP_ASYNC16(d, W + (size_t)wr * ldw + k0);
        }
    };

#pragma unroll
    for (int s = 0; s < BIG_NST-1; s++) {
        if (s < nchunk) load_stage(s, s);
        CP_COMMIT();
    }

    for (int kt = 0; kt < nchunk; kt++) {
        const int st = kt % BIG_NST;
        const __half* cA = sAb + st * 128 * SAST;
        const __half* cB = sBb + st * 128 * SAST;
        asm volatile("cp.async.wait_group %0;" :: "n"(BIG_NST-2) : "memory");
        __syncthreads();
        if (kt + BIG_NST-1 < nchunk) load_stage((kt + BIG_NST-1) % BIG_NST, kt + BIG_NST-1);
        CP_COMMIT();

#pragma unroll
        for (int ks = 0; ks < 2; ks++) {
            const int kb = ks << 4;
            uint32_t af[4][4], bf[4][2];
#pragma unroll
            for (int mt = 0; mt < 4; mt++) {
                uint32_t sa = (uint32_t)__cvta_generic_to_shared(
                    &cA[(wm + mt*16 + a_row) * SAST + kb + a_koff]);
                LDSM_X4(af[mt][0], af[mt][1], af[mt][2], af[mt][3], sa);
            }
#pragma unroll
            for (int ntp = 0; ntp < 2; ntp++) {
                uint32_t sbN = (uint32_t)__cvta_generic_to_shared(
                    &cB[(wn + ntp*16 + b_row) * SAST + kb + b_koff]);
                LDSM_X4(bf[2*ntp][0], bf[2*ntp][1], bf[2*ntp+1][0], bf[2*ntp+1][1], sbN);
            }
#pragma unroll
            for (int mt = 0; mt < 4; mt++)
#pragma unroll
                for (int nt = 0; nt < 4; nt++) MMA_F16(acc[mt][nt], af[mt], bf[nt]);
        }
    }
    CP_WAIT0();

#pragma unroll
    for (int mt = 0; mt < 4; mt++) {
        const int r0 = m0 + wm + mt*16 + g;
        float bc0 = 0.f, bc1 = 0.f;
        if (EPI == 3) { bc0 = ep.bc[r0]; bc1 = ep.bc[r0 + 8]; }
#pragma unroll
        for (int nt = 0; nt < 4; nt++) {
            const int cb = n0 + wn + nt*8 + th*2;
            if (cb >= N) continue;
            float2 v0 = make_float2(acc[mt][nt][0], acc[mt][nt][1]);
            float2 v1 = make_float2(acc[mt][nt][2], acc[mt][nt][3]);
            epi_store<EPI>(r0, cb, N, v0, v1, bias, C, ep, bc0, bc1);
        }
    }
}

// ================= dbc split-K reduce + bc = dot(B,C) ============================
__global__ __launch_bounds__(96) void reduce_dbc_bc(
    const float* __restrict__ part, __half* __restrict__ dbch, float* __restrict__ bc)
{
    const int b = blockIdx.x;
    const int t = threadIdx.x;
    const int idx = b * 96 + t;
    float v = part[idx] + part[BATCH*96 + idx] + part[2*BATCH*96 + idx] + part[3*BATCH*96 + idx];
    dbch[idx] = __float2half_rn(v);
    __shared__ float sm[32];
    if (t >= 64) sm[t - 64] = v;
    __syncthreads();
    if (t == 0) {
        float s = 0.f;
#pragma unroll
        for (int i = 0; i < 16; i++) s += sm[i] * sm[16 + i];
        bc[b] = s;
    }
}

// ================= LayerNorm: warp per row, register-cached single pass ==========
__device__ __forceinline__ void ln_row(
    const float* __restrict__ x, const float* __restrict__ r,
    const float* __restrict__ g, const float* __restrict__ b,
    float* __restrict__ y, __half* __restrict__ yh, int cols, int lane)
{
    const int n4 = cols >> 2;
    const int nit = n4 >> 5;
    const float4* x4 = (const float4*)x;
    const float4* r4 = (const float4*)r;
    float4 buf[8];
    float s = 0.f, q = 0.f;
#pragma unroll
    for (int i = 0; i < 8; i++) {
        if (i < nit) {
            float4 v = x4[lane + (i << 5)];
            if (r) { float4 rr = r4[lane + (i << 5)]; v.x += rr.x; v.y += rr.y; v.z += rr.z; v.w += rr.w; }
            buf[i] = v;
            s += v.x + v.y + v.z + v.w;
            q += v.x*v.x + v.y*v.y + v.z*v.z + v.w*v.w;
        }
    }
#pragma unroll
    for (int o = 16; o; o >>= 1) {
        s += __shfl_xor_sync(0xFFFFFFFFu, s, o);
        q += __shfl_xor_sync(0xFFFFFFFFu, q, o);
    }
    const float m = s / cols;
    const float rs = rsqrtf(q / cols - m * m + 1e-5f);
    const float4* g4 = (const float4*)g;
    const float4* b4 = (const float4*)b;
    float4* y4 = (float4*)y;
#pragma unroll
    for (int i = 0; i < 8; i++) {
        if (i < nit) {
            float4 v = buf[i];
            float4 gg = g4[lane + (i << 5)], bb = b4[lane + (i << 5)];
            v.x = (v.x - m) * rs * gg.x + bb.x;
            v.y = (v.y - m) * rs * gg.y + bb.y;
            v.z = (v.z - m) * rs * gg.z + bb.z;
            v.w = (v.w - m) * rs * gg.w + bb.w;
            y4[lane + (i << 5)] = v;
            if (yh) {
                __half2 lo = __floats2half2_rn(v.x, v.y), hi = __floats2half2_rn(v.z, v.w);
                uint2 u; u.x = *(uint32_t*)&lo; u.y = *(uint32_t*)&hi;
                *(uint2*)(yh + ((size_t)(lane + (i << 5)) << 2)) = u;
            }
        }
    }
}

__global__ __launch_bounds__(128) void ln_warp(
    const float* __restrict__ X, const float* __restrict__ R,
    const float* __restrict__ g, const float* __restrict__ b,
    float* __restrict__ Y, __half* __restrict__ Yh, int cols)
{
    const int row = blockIdx.x * 4 + (threadIdx.x >> 5);
    ln_row(X + (size_t)row * cols, R ? R + (size_t)row * cols : nullptr,
           g, b, Y + (size_t)row * cols, Yh ? Yh + (size_t)row * cols : nullptr,
           cols, threadIdx.x & 31);
}

__global__ __launch_bounds__(128) void ln_warp2(
    const float* __restrict__ X0, const float* __restrict__ X1,
    const float* __restrict__ g0, const float* __restrict__ g1,
    const float* __restrict__ b0, const float* __restrict__ b1,
    float* __restrict__ Y0, float* __restrict__ Y1,
    __half* __restrict__ Y0h, __half* __restrict__ Y1h, int cols)
{
    const int row = blockIdx.x * 4 + (threadIdx.x >> 5);
    const float* X = blockIdx.y ? X1 : X0;
    const float* g = blockIdx.y ? g1 : g0;
    const float* b = blockIdx.y ? b1 : b0;
    float* Y  = blockIdx.y ? Y1 : Y0;
    __half* Yh = blockIdx.y ? Y1h : Y0h;
    ln_row(X + (size_t)row * cols, nullptr, g, b,
           Y + (size_t)row * cols, Yh + (size_t)row * cols, cols, threadIdx.x & 31);
}

// ================= gate logits + softmax + gated concat ==========================
__global__ __launch_bounds__(256) void gate_finalize(
    const float* __restrict__ h2, const float* __restrict__ w3, const float* __restrict__ b3,
    const float* __restrict__ img, const float* __restrict__ txt,
    float* __restrict__ gate_out, float* __restrict__ x_out, __half* __restrict__ xh_out)
{
    const int b = blockIdx.x;
    const int tid = threadIdx.x;
    __shared__ float r0[256], r1[256];
    __shared__ float gs[2];
    float h = h2[b * 256 + tid];
    r0[tid] = h * w3[tid];
    r1[tid] = h * w3[256 + tid];
    __syncthreads();
    for (int o = 128; o; o >>= 1) {
        if (tid < o) { r0[tid] += r0[tid + o]; r1[tid] += r1[tid + o]; }
        __syncthreads();
    }
    if (tid == 0) {
        float l0 = r0[0] + b3[0], l1 = r1[0] + b3[1];
        float mx = fmaxf(l0, l1);
        float e0 = expf(l0 - mx), e1 = expf(l1 - mx);
        float inv = 1.f / (e0 + e1);
        gs[0] = e0 * inv; gs[1] = e1 * inv;
        gate_out[b * 2 + 0] = gs[0]; gate_out[b * 2 + 1] = gs[1];
    }
    __syncthreads();
    float g0 = gs[0], g1 = gs[1];
    for (int c = tid; c < DMH; c += 256) {
        float v = (c < DIMF) ? g0 * img[b * DIMF + c] : g1 * txt[b * DIMF + c - DIMF];
        x_out[b * DMH + c] = v;
        xh_out[b * DMH + c] = __float2half_rn(v);
    }
}

// ================= host side ======================================================
static inline void* symv(const void* s)
{
    void* p = nullptr;
    cudaGetSymbolAddress(&p, s);
    return p;
}

extern "C" void kernel_launch(void* const* d_in, const int* in_sizes, int n_in,
                              void* d_out, int out_size)
{
    cudaFuncSetAttribute(gemm_big<2>, cudaFuncAttributeMaxDynamicSharedMemorySize, BIG_SMEM);

    const float* image   = (const float*)d_in[0];
    const float* text    = (const float*)d_in[1];
    const float* img_w   = (const float*)d_in[2];
    const float* img_b   = (const float*)d_in[3];
    const float* img_g   = (const float*)d_in[4];
    const float* img_bt  = (const float*)d_in[5];
    const float* txt_w   = (const float*)d_in[6];
    const float* txt_b   = (const float*)d_in[7];
    const float* txt_g   = (const float*)d_in[8];
    const float* txt_bt  = (const float*)d_in[9];
    const float* gate_w1 = (const float*)d_in[10];
    const float* gate_b1 = (const float*)d_in[11];
    const float* gate_w2 = (const float*)d_in[12];
    const float* gate_b2 = (const float*)d_in[13];
    const float* gate_w3 = (const float*)d_in[14];
    const float* gate_b3 = (const float*)d_in[15];
    const float* in_proj = (const float*)d_in[16];
    const float* conv_w  = (const float*)d_in[17];
    const float* conv_b  = (const float*)d_in[18];
    const float* x_proj  = (const float*)d_in[19];
    const float* dt_w    = (const float*)d_in[20];
    const float* dt_b    = (const float*)d_in[21];
    /* d_in[22] = A_log : dead (L=1, h0=0) */
    const float* D_par   = (const float*)d_in[23];
    const float* out_w   = (const float*)d_in[24];
    const float* mn_g    = (const float*)d_in[25];
    const float* mn_b    = (const float*)d_in[26];
    const float* fc_w    = (const float*)d_in[27];
    const float* fc_b    = (const float*)d_in[28];
    const float* fin_g   = (const float*)d_in[29];
    const float* fin_b   = (const float*)d_in[30];

    float* out = (float*)d_out;

    float*  f0   = (float*)symv(g_f0);   float*  f1   = (float*)symv(g_f1);
    float*  t0   = (float*)symv(g_t0);   float*  t1   = (float*)symv(g_t1);
    __half* f0h  = (__half*)symv(g_f0h); __half* t0h  = (__half*)symv(g_t0h);
    __half* h1h  = (__half*)symv(g_h1h); float*  h2   = (float*)symv(g_h2);
    float*  x    = (float*)symv(g_x);    __half* xh   = (__half*)symv(g_xh);
    float*  z    = (float*)symv(g_z);
    float*  xc   = (float*)symv(g_xc);   __half* xch  = (__half*)symv(g_xch);
    float*  dbcp = (float*)symv(g_dbcp); __half* dbch = (__half*)symv(g_dbch);
    float*  bc   = (float*)symv(g_bc);   __half* yh   = (__half*)symv(g_yh);
    float*  mo   = (float*)symv(g_mo);   float*  fc   = (float*)symv(g_fc);
    __half* wh   = (__half*)symv(g_wh);

    const int fused_elems = BATCH * 256;
    float* gate_out = (out_size >= fused_elems + BATCH * 2) ? (out + fused_elems)
                                                            : (float*)symv(g_gate_dummy);

    Epi ep0 = {};

    // ---- convert all weights + inputs to fp16 (identical numerics to in-GEMM cvt) ----
    cvt_all<<<(W_TOTAL/4 + 255)/256, 256>>>(
        img_w, txt_w, gate_w1, gate_w2, in_proj, x_proj, dt_w, out_w, fc_w,
        image, text);

    // ---- alignment towers: batched img/txt GEMM + batched LN ----
    const __half* a_img = wh + W_IMAGE;
    const __half* a_txt = wh + W_TEXT;
    for (int i = 0; i < 3; i++) {
        gemm_h<64,1><<<dim3(8,16,2), 128>>>(
            a_img, a_txt, DIMF,
            wh + W_IMG + (size_t)i*DIMF*DIMF, wh + W_TXT + (size_t)i*DIMF*DIMF, DIMF,
            img_b + i*DIMF, txt_b + i*DIMF,
            f1, t1, DIMF, DIMF, 1, 0, ep0);
        ln_warp2<<<dim3(BATCH/4, 2), 128>>>(
            f1, t1, img_g + i*DIMF, txt_g + i*DIMF,
            img_bt + i*DIMF, txt_bt + i*DIMF, f0, t0, f0h, t0h, DIMF);
        a_img = f0h; a_txt = t0h;
    }

    // ---- gating MLP (concat folded into W1 GEMM via zmode=3) ----
    gemm_h<64,4><<<dim3(8,16), 128>>>(f0h, t0h, DIMF, wh + W_G1, nullptr, DMH,
                                      gate_b1, nullptr, (float*)h1h, nullptr, DIMF, DMH, 3, 0, ep0);
    gemm_h<64,1><<<dim3(4,16), 128>>>(h1h, nullptr, DIMF, wh + W_G2, nullptr, DIMF,
                                      gate_b2, nullptr, h2, nullptr, 256, DIMF, 0, 0, ep0);
    gate_finalize<<<BATCH, 256>>>(h2, gate_w3, gate_b3, f0, t0, gate_out, x, xh);

    // ---- 3 Mamba layers (L=1, SSM collapsed, heavily fused) ----
    for (int i = 0; i < 3; i++) {
        // in_proj + conv(L=1) + silu fused: big 128x128 tile, 4-stage
        Epi epc = {};
        epc.cw  = conv_w + (size_t)i*DIH*4;
        epc.cbv = conv_b + (size_t)i*DIH;
        epc.xc  = xc;  epc.xch = xch;  epc.z = z;
        gemm_big<2><<<dim3(32,8), 256, BIG_SMEM>>>(
            xh, DMH, wh + W_INP + (size_t)i*2*DIH*DMH, DMH,
            nullptr, nullptr, 2*DIH, DMH, epc);

        // dbc = xc @ x_proj^T  (N=96), split-K=4 into partials, then reduce + bc
        gemm_h<64,0><<<dim3(2,16,4), 128>>>(
            xch, nullptr, DIH, wh + W_XPJ + (size_t)i*96*DIH, nullptr, DIH,
            nullptr, nullptr, dbcp, nullptr, 96, DIH/4, 2, BATCH*96, ep0);
        reduce_dbc_bc<<<BATCH, 96>>>(dbcp, dbch, bc);

        // dt GEMM + full collapsed-SSM epilogue -> y (fp16)
        Epi epy = {};
        epy.xcin = xc; epy.zin = z;
        epy.Dp = D_par + (size_t)i*DIH; epy.bc = bc;
        gemm_h<128,3><<<dim3(32,8), 256>>>(
            dbch, nullptr, 96, wh + W_DTW + (size_t)i*DIH*DTRH, nullptr, DTRH,
            dt_b + (size_t)i*DIH, nullptr, (float*)yh, nullptr, DIH, DTRH, 0, 0, epy);

        // out_proj: TM=64 tiles -> 256 CTAs (was 128, grid-starved)
        gemm_h<64,0><<<dim3(16,16), 128>>>(
            yh, nullptr, DIH, wh + W_OUT + (size_t)i*DMH*DIH, nullptr, DIH,
            nullptr, nullptr, mo, nullptr, DMH, DIH, 0, 0, ep0);

        // residual + LN (fp32 + fp16 copies)
        ln_warp<<<BATCH/4, 128>>>(mo, x, mn_g + (size_t)i*DMH, mn_b + (size_t)i*DMH, x, xh, DMH);
    }

    // ---- head ----
    gemm_h<64,0><<<dim3(4,16), 128>>>(xh, nullptr, DMH, wh + W_FC, nullptr, DMH,
                                      fc_b, nullptr, fc, nullptr, 256, DMH, 0, 0, ep0);
    ln_warp<<<BATCH/4, 128>>>(fc, nullptr, fin_g, fin_b, out, nullptr, 256);
}